// round 1
// baseline (speedup 1.0000x reference)
#include <cuda_runtime.h>

#define BATCH  8
#define SEQ    1024
#define DMODEL 768
#define NHEAD  12
#define DHEAD  64
#define MT     (BATCH*SEQ)   // 8192 rows

// Scratch (device globals: no allocations allowed in kernel_launch)
__device__ float g_Q[MT*DMODEL];
__device__ float g_K[MT*DMODEL];
__device__ float g_V[MT*DMODEL];
__device__ float g_C[MT*DMODEL];

// ---------------------------------------------------------------------------
// GEMM: Y[M,768] = X[M,768] @ W[768,768]^T + bias   (both row-major, NT)
// 128x128 tile, BK=16, 256 threads, 8x8 micro-tile per thread.
// ---------------------------------------------------------------------------
__global__ __launch_bounds__(256) void gemm_nt_bias(
    const float* __restrict__ X, const float* __restrict__ W,
    const float* __restrict__ bias, float* __restrict__ Y)
{
    __shared__ float Xs[16][132];
    __shared__ float Ws[16][132];
    const int bm = blockIdx.y * 128;
    const int bn = blockIdx.x * 128;
    const int t  = threadIdx.x;
    const int tx = t & 15;
    const int ty = t >> 4;
    const int lr = t >> 1;          // 0..127 : tile row this thread loads
    const int lq = (t & 1) * 8;     // 0 or 8 : k-offset this thread loads

    const float* Xp = X + (bm + lr) * DMODEL + lq;
    const float* Wp = W + (bn + lr) * DMODEL + lq;

    float acc[8][8];
#pragma unroll
    for (int i = 0; i < 8; ++i)
#pragma unroll
        for (int j = 0; j < 8; ++j) acc[i][j] = 0.f;

    for (int k0 = 0; k0 < DMODEL; k0 += 16) {
        float4 x0 = *(const float4*)(Xp + k0);
        float4 x1 = *(const float4*)(Xp + k0 + 4);
        float4 w0 = *(const float4*)(Wp + k0);
        float4 w1 = *(const float4*)(Wp + k0 + 4);
        __syncthreads();
        Xs[lq+0][lr]=x0.x; Xs[lq+1][lr]=x0.y; Xs[lq+2][lr]=x0.z; Xs[lq+3][lr]=x0.w;
        Xs[lq+4][lr]=x1.x; Xs[lq+5][lr]=x1.y; Xs[lq+6][lr]=x1.z; Xs[lq+7][lr]=x1.w;
        Ws[lq+0][lr]=w0.x; Ws[lq+1][lr]=w0.y; Ws[lq+2][lr]=w0.z; Ws[lq+3][lr]=w0.w;
        Ws[lq+4][lr]=w1.x; Ws[lq+5][lr]=w1.y; Ws[lq+6][lr]=w1.z; Ws[lq+7][lr]=w1.w;
        __syncthreads();
#pragma unroll
        for (int kk = 0; kk < 16; ++kk) {
            float a[8], b[8];
            *(float4*)&a[0] = *(const float4*)&Xs[kk][ty*8];
            *(float4*)&a[4] = *(const float4*)&Xs[kk][ty*8+4];
            *(float4*)&b[0] = *(const float4*)&Ws[kk][tx*8];
            *(float4*)&b[4] = *(const float4*)&Ws[kk][tx*8+4];
#pragma unroll
            for (int i = 0; i < 8; ++i)
#pragma unroll
                for (int j = 0; j < 8; ++j)
                    acc[i][j] += a[i]*b[j];
        }
    }

#pragma unroll
    for (int i = 0; i < 8; ++i) {
        float* Yp = Y + (bm + ty*8 + i)*DMODEL + bn + tx*8;
#pragma unroll
        for (int j = 0; j < 8; j += 4) {
            float4 bv = *(const float4*)(bias + bn + tx*8 + j);
            float4 r;
            r.x = acc[i][j+0] + bv.x;
            r.y = acc[i][j+1] + bv.y;
            r.z = acc[i][j+2] + bv.z;
            r.w = acc[i][j+3] + bv.w;
            *(float4*)(Yp + j) = r;
        }
    }
}

// ---------------------------------------------------------------------------
// Fused attention with head-axis softmax.
// attn[b,h,n,m] = exp(s[b,h,n,m]*sc) / sum_h' exp(s[b,h',n,m]*sc)
// This is LOCAL per (n,m): stream over m-tiles, no global softmax state.
// One block = (batch b, 32 rows of n). 256 threads.
// ---------------------------------------------------------------------------
#define NT   32
#define WB_S 33   // padded stride for weight buffer
#define KV_S 68   // padded stride for K/V head tile

struct AttnSmem {
    float Qs[NT][DMODEL];        // 98304 B  (resident Q tile, all heads)
    float Wb[NHEAD][NT][WB_S];   // 50688 B  (exp-weights per head)
    float KV[NT][KV_S];          //  8704 B  (current head's K or V tile)
};
#define ATTN_SMEM_BYTES (sizeof(AttnSmem))

__global__ __launch_bounds__(256) void attn_kernel()
{
    extern __shared__ char smem_raw[];
    AttnSmem& sm = *reinterpret_cast<AttnSmem*>(smem_raw);
    const int b  = blockIdx.y;
    const int n0 = blockIdx.x * NT;
    const int t  = threadIdx.x;

    const float* Qb = g_Q + (b*SEQ + n0)*DMODEL;
    const float* Kb = g_K + b*SEQ*DMODEL;
    const float* Vb = g_V + b*SEQ*DMODEL;

    // Load resident Q tile (32 x 768)
    for (int i = t; i < NT*(DMODEL/4); i += 256) {
        int r = i / (DMODEL/4);
        int c = i % (DMODEL/4);
        ((float4*)sm.Qs[r])[c] = ((const float4*)(Qb + r*DMODEL))[c];
    }

    // score-phase mapping: 2x2 micro-tile at (tn,tn+16) x (tm,tm+16)
    const int tn = t >> 4;        // 0..15
    const int tm = t & 15;        // 0..15
    // O-phase mapping: row on, 8 cols starting at od (per head)
    const int on = t >> 3;        // 0..31
    const int od = (t & 7) * 8;   // 0,8,..,56

    float o[NHEAD*8];
#pragma unroll
    for (int i = 0; i < NHEAD*8; ++i) o[i] = 0.f;

    const int lvr = t >> 3;        // KV-tile load row 0..31
    const int lvc = (t & 7) * 2;   // KV-tile load float4 col

    for (int m0 = 0; m0 < SEQ; m0 += NT) {
        float z00 = 0.f, z01 = 0.f, z10 = 0.f, z11 = 0.f;

        // ---- scores for all 12 heads over this m-tile ----
        for (int h = 0; h < NHEAD; ++h) {
            __syncthreads();   // protect KV from previous readers
            {
                const float4* src = (const float4*)(Kb + (m0 + lvr)*DMODEL + h*DHEAD);
                float4* dst = (float4*)sm.KV[lvr];
                dst[lvc]   = src[lvc];
                dst[lvc+1] = src[lvc+1];
            }
            __syncthreads();

            float s00=0.f, s01=0.f, s10=0.f, s11=0.f;
            const float* q0  = &sm.Qs[tn][h*DHEAD];
            const float* q1  = &sm.Qs[tn+16][h*DHEAD];
            const float* k0p = sm.KV[tm];
            const float* k1p = sm.KV[tm+16];
#pragma unroll
            for (int d = 0; d < DHEAD; d += 4) {
                float4 a0 = *(const float4*)(q0 + d);
                float4 a1 = *(const float4*)(q1 + d);
                float4 c0 = *(const float4*)(k0p + d);
                float4 c1 = *(const float4*)(k1p + d);
                s00 += a0.x*c0.x + a0.y*c0.y + a0.z*c0.z + a0.w*c0.w;
                s01 += a0.x*c1.x + a0.y*c1.y + a0.z*c1.z + a0.w*c1.w;
                s10 += a1.x*c0.x + a1.y*c0.y + a1.z*c0.z + a1.w*c0.w;
                s11 += a1.x*c1.x + a1.y*c1.y + a1.z*c1.z + a1.w*c1.w;
            }
            const float SC = 0.125f;   // 1/sqrt(64)
            float w00 = __expf(s00*SC);
            float w01 = __expf(s01*SC);
            float w10 = __expf(s10*SC);
            float w11 = __expf(s11*SC);
            z00 += w00; z01 += w01; z10 += w10; z11 += w11;
            sm.Wb[h][tn][tm]       = w00;
            sm.Wb[h][tn][tm+16]    = w01;
            sm.Wb[h][tn+16][tm]    = w10;
            sm.Wb[h][tn+16][tm+16] = w11;
        }

        // ---- normalize (each thread owns exactly the entries it wrote) ----
        float i00 = 1.f/z00, i01 = 1.f/z01, i10 = 1.f/z10, i11 = 1.f/z11;
#pragma unroll
        for (int h = 0; h < NHEAD; ++h) {
            sm.Wb[h][tn][tm]       *= i00;
            sm.Wb[h][tn][tm+16]    *= i01;
            sm.Wb[h][tn+16][tm]    *= i10;
            sm.Wb[h][tn+16][tm+16] *= i11;
        }

        // ---- O += A_h @ V_h per head ----
#pragma unroll
        for (int h = 0; h < NHEAD; ++h) {
            __syncthreads();   // also publishes normalized Wb on h==0
            {
                const float4* src = (const float4*)(Vb + (m0 + lvr)*DMODEL + h*DHEAD);
                float4* dst = (float4*)sm.KV[lvr];
                dst[lvc]   = src[lvc];
                dst[lvc+1] = src[lvc+1];
            }
            __syncthreads();

            float* oh = &o[h*8];
#pragma unroll 8
            for (int m = 0; m < NT; ++m) {
                float w = sm.Wb[h][on][m];
                float4 v0 = *(const float4*)&sm.KV[m][od];
                float4 v1 = *(const float4*)&sm.KV[m][od+4];
                oh[0] += w*v0.x; oh[1] += w*v0.y; oh[2] += w*v0.z; oh[3] += w*v0.w;
                oh[4] += w*v1.x; oh[5] += w*v1.y; oh[6] += w*v1.z; oh[7] += w*v1.w;
            }
        }
    }

    // ---- writeback context: C[b, n0+on, h*64+od .. +8] ----
    float* Cb = g_C + (b*SEQ + n0 + on)*DMODEL + od;
#pragma unroll
    for (int h = 0; h < NHEAD; ++h) {
        float4 r0, r1;
        r0.x=o[h*8+0]; r0.y=o[h*8+1]; r0.z=o[h*8+2]; r0.w=o[h*8+3];
        r1.x=o[h*8+4]; r1.y=o[h*8+5]; r1.z=o[h*8+6]; r1.w=o[h*8+7];
        *(float4*)(Cb + h*DHEAD)     = r0;
        *(float4*)(Cb + h*DHEAD + 4) = r1;
    }
}

// ---------------------------------------------------------------------------
extern "C" void kernel_launch(void* const* d_in, const int* in_sizes, int n_in,
                              void* d_out, int out_size)
{
    const float* x  = (const float*)d_in[0];
    const float* Wq = (const float*)d_in[1];
    const float* bq = (const float*)d_in[2];
    const float* Wk = (const float*)d_in[3];
    const float* bk = (const float*)d_in[4];
    const float* Wv = (const float*)d_in[5];
    const float* bv = (const float*)d_in[6];
    const float* Wo = (const float*)d_in[7];
    const float* bo = (const float*)d_in[8];
    float* out = (float*)d_out;

    float *Q, *K, *V, *C;
    cudaGetSymbolAddress((void**)&Q, g_Q);
    cudaGetSymbolAddress((void**)&K, g_K);
    cudaGetSymbolAddress((void**)&V, g_V);
    cudaGetSymbolAddress((void**)&C, g_C);

    cudaFuncSetAttribute(attn_kernel,
                         cudaFuncAttributeMaxDynamicSharedMemorySize,
                         (int)ATTN_SMEM_BYTES);

    dim3 gg(DMODEL/128, MT/128);   // (6, 64)
    gemm_nt_bias<<<gg, 256>>>(x, Wq, bq, Q);
    gemm_nt_bias<<<gg, 256>>>(x, Wk, bk, K);
    gemm_nt_bias<<<gg, 256>>>(x, Wv, bv, V);

    attn_kernel<<<dim3(SEQ/NT, BATCH), 256, ATTN_SMEM_BYTES>>>();

    gemm_nt_bias<<<gg, 256>>>(C, Wo, bo, out);
}

// round 2
// speedup vs baseline: 1.9748x; 1.9748x over previous
#include <cuda_runtime.h>

#define BATCH  8
#define SEQ    1024
#define DM     768
#define NHEAD  12
#define DHEAD  64
#define MTOT   (BATCH*SEQ)

// Scratch (device globals: no allocations allowed)
__device__ float g_Q[MTOT*DM];
__device__ float g_K[MTOT*DM];
__device__ float g_V[MTOT*DM];
__device__ float g_C[MTOT*DM];

// ---------------------------------------------------------------------------
// GEMM: Y[M,768] = X[M,768] @ W[768,768]^T + bias  (NT, row-major)
// 128x128 tile, BK=16, 256 threads, 8x8 micro-tile, reg double-buffered LDG.
// ---------------------------------------------------------------------------
__device__ __forceinline__ void gemm_body(
    const float* __restrict__ X, const float* __restrict__ W,
    const float* __restrict__ bias, float* __restrict__ Y,
    int bm, int bn, float Xs[16][132], float Ws[16][132])
{
    const int t  = threadIdx.x;
    const int tx = t & 15;
    const int ty = t >> 4;
    const int lr = t >> 1;
    const int lq = (t & 1) * 8;

    const float* Xp = X + (bm + lr) * DM + lq;
    const float* Wp = W + (bn + lr) * DM + lq;

    float acc[8][8];
#pragma unroll
    for (int i = 0; i < 8; ++i)
#pragma unroll
        for (int j = 0; j < 8; ++j) acc[i][j] = 0.f;

    float4 x0 = *(const float4*)(Xp);
    float4 x1 = *(const float4*)(Xp + 4);
    float4 w0 = *(const float4*)(Wp);
    float4 w1 = *(const float4*)(Wp + 4);

    for (int k0 = 0; k0 < DM; k0 += 16) {
        __syncthreads();
        Xs[lq+0][lr]=x0.x; Xs[lq+1][lr]=x0.y; Xs[lq+2][lr]=x0.z; Xs[lq+3][lr]=x0.w;
        Xs[lq+4][lr]=x1.x; Xs[lq+5][lr]=x1.y; Xs[lq+6][lr]=x1.z; Xs[lq+7][lr]=x1.w;
        Ws[lq+0][lr]=w0.x; Ws[lq+1][lr]=w0.y; Ws[lq+2][lr]=w0.z; Ws[lq+3][lr]=w0.w;
        Ws[lq+4][lr]=w1.x; Ws[lq+5][lr]=w1.y; Ws[lq+6][lr]=w1.z; Ws[lq+7][lr]=w1.w;
        __syncthreads();
        if (k0 + 16 < DM) {
            x0 = *(const float4*)(Xp + k0 + 16);
            x1 = *(const float4*)(Xp + k0 + 20);
            w0 = *(const float4*)(Wp + k0 + 16);
            w1 = *(const float4*)(Wp + k0 + 20);
        }
#pragma unroll
        for (int kk = 0; kk < 16; ++kk) {
            float a[8], bb[8];
            *(float4*)&a[0]  = *(const float4*)&Xs[kk][ty*8];
            *(float4*)&a[4]  = *(const float4*)&Xs[kk][ty*8+4];
            *(float4*)&bb[0] = *(const float4*)&Ws[kk][tx*8];
            *(float4*)&bb[4] = *(const float4*)&Ws[kk][tx*8+4];
#pragma unroll
            for (int i = 0; i < 8; ++i)
#pragma unroll
                for (int j = 0; j < 8; ++j)
                    acc[i][j] += a[i]*bb[j];
        }
    }

#pragma unroll
    for (int i = 0; i < 8; ++i) {
        float* Yp = Y + (bm + ty*8 + i)*DM + bn + tx*8;
#pragma unroll
        for (int j = 0; j < 8; j += 4) {
            float4 bv = *(const float4*)(bias + bn + tx*8 + j);
            float4 r;
            r.x = acc[i][j+0] + bv.x;
            r.y = acc[i][j+1] + bv.y;
            r.z = acc[i][j+2] + bv.z;
            r.w = acc[i][j+3] + bv.w;
            *(float4*)(Yp + j) = r;
        }
    }
}

__global__ __launch_bounds__(256) void gemm_qkv(
    const float* __restrict__ X,
    const float* __restrict__ Wq, const float* __restrict__ bq,
    const float* __restrict__ Wk, const float* __restrict__ bk,
    const float* __restrict__ Wv, const float* __restrict__ bv)
{
    __shared__ float Xs[16][132];
    __shared__ float Ws[16][132];
    const float* W; const float* bb; float* Y;
    if (blockIdx.z == 0)      { W = Wq; bb = bq; Y = g_Q; }
    else if (blockIdx.z == 1) { W = Wk; bb = bk; Y = g_K; }
    else                      { W = Wv; bb = bv; Y = g_V; }
    gemm_body(X, W, bb, Y, blockIdx.y*128, blockIdx.x*128, Xs, Ws);
}

__global__ __launch_bounds__(256) void gemm_single(
    const float* __restrict__ X, const float* __restrict__ W,
    const float* __restrict__ bias, float* __restrict__ Y)
{
    __shared__ float Xs[16][132];
    __shared__ float Ws[16][132];
    gemm_body(X, W, bias, Y, blockIdx.y*128, blockIdx.x*128, Xs, Ws);
}

// ---------------------------------------------------------------------------
// Fused attention, softmax over the HEAD axis (local per (n,m) pair).
// Block = (batch, 32 n-rows), 256 threads = 4 groups x 64 threads.
// Group g owns heads {g, g+4, g+8}. Score micro-tile 4x4, O micro-tile 4x8.
// smem: Qt[768][32] (transposed Q), Wt[12][32][33] (weights, m-major),
//       zb[32][33] (head-sum), KV[8 slots][2112] (Kt [64][33] or V [32][64]).
// ---------------------------------------------------------------------------
#define QT_OFF 0
#define WT_OFF 24576
#define ZB_OFF 37248
#define KV_OFF 38304
#define KVSLOT 2112
#define SMEM_FLOATS 55200
#define ATTN_SMEM_BYTES (SMEM_FLOATS*4)

__device__ __forceinline__ void score_head(
    const float* __restrict__ qt,   // Qt + h*64*32 + r0
    const float* __restrict__ kt,   // KV + slot*KVSLOT + c0
    float w[4][4], float zr[4][4])
{
    float s[4][4];
#pragma unroll
    for (int i = 0; i < 4; ++i)
#pragma unroll
        for (int j = 0; j < 4; ++j) s[i][j] = 0.f;

#pragma unroll 8
    for (int d = 0; d < DHEAD; ++d) {
        float4 q4 = *(const float4*)(qt + d*32);
        float k0_ = kt[d*33 + 0];
        float k1_ = kt[d*33 + 1];
        float k2_ = kt[d*33 + 2];
        float k3_ = kt[d*33 + 3];
        s[0][0]+=q4.x*k0_; s[0][1]+=q4.x*k1_; s[0][2]+=q4.x*k2_; s[0][3]+=q4.x*k3_;
        s[1][0]+=q4.y*k0_; s[1][1]+=q4.y*k1_; s[1][2]+=q4.y*k2_; s[1][3]+=q4.y*k3_;
        s[2][0]+=q4.z*k0_; s[2][1]+=q4.z*k1_; s[2][2]+=q4.z*k2_; s[2][3]+=q4.z*k3_;
        s[3][0]+=q4.w*k0_; s[3][1]+=q4.w*k1_; s[3][2]+=q4.w*k2_; s[3][3]+=q4.w*k3_;
    }
#pragma unroll
    for (int i = 0; i < 4; ++i)
#pragma unroll
        for (int j = 0; j < 4; ++j) {
            float e = __expf(s[i][j]*0.125f);
            w[i][j] = e;
            zr[i][j] += e;
        }
}

__device__ __forceinline__ void o_accum(
    const float* __restrict__ wt,   // Wt + h*1056 + r0
    const float* __restrict__ vv,   // KV + slot*KVSLOT + d0
    float o[4][8])
{
#pragma unroll 8
    for (int m = 0; m < 32; ++m) {
        float4 v0 = *(const float4*)(vv + m*64);
        float4 v1 = *(const float4*)(vv + m*64 + 4);
        float va[8] = {v0.x,v0.y,v0.z,v0.w,v1.x,v1.y,v1.z,v1.w};
#pragma unroll
        for (int i = 0; i < 4; ++i) {
            float wi = wt[m*33 + i];
#pragma unroll
            for (int k = 0; k < 8; ++k) o[i][k] += wi*va[k];
        }
    }
}

__global__ __launch_bounds__(256) void attn_kernel()
{
    extern __shared__ float smf[];
    float* Qt = smf + QT_OFF;
    float* Wt = smf + WT_OFF;
    float* zb = smf + ZB_OFF;
    float* KV = smf + KV_OFF;

    const int b  = blockIdx.y;
    const int n0 = blockIdx.x * 32;
    const int t  = threadIdx.x;
    const int g  = t >> 6;
    const int u  = t & 63;
    const int gr = u >> 3;
    const int gc = u & 7;
    const int r0 = gr*4, c0 = gc*4, d0 = gc*8;

    const float* Qb = g_Q + (size_t)(b*SEQ + n0)*DM;
    const float* Kb = g_K + (size_t)b*SEQ*DM;
    const float* Vb = g_V + (size_t)b*SEQ*DM;

    // Load Q transposed: Qt[d][r], stride 32 (conflict-free stores & loads)
    {
        const int rl = t & 31, cb = t >> 5;
#pragma unroll
        for (int q = 0; q < 24; ++q) {
            int c4 = cb + q*8;                       // 0..191
            float4 v = *(const float4*)(Qb + rl*DM + c4*4);
            Qt[(c4*4+0)*32 + rl] = v.x;
            Qt[(c4*4+1)*32 + rl] = v.y;
            Qt[(c4*4+2)*32 + rl] = v.z;
            Qt[(c4*4+3)*32 + rl] = v.w;
        }
    }

    float o[3][4][8];
#pragma unroll
    for (int hh = 0; hh < 3; ++hh)
#pragma unroll
        for (int i = 0; i < 4; ++i)
#pragma unroll
            for (int k = 0; k < 8; ++k) o[hh][i][k] = 0.f;

    for (int m0 = 0; m0 < SEQ; m0 += 32) {
        // ---- phase 0: zero zb, stage Kt heads 0..7 (transposed, stride 33)
        __syncthreads();
        for (int i = t; i < 1056; i += 256) zb[i] = 0.f;
#pragma unroll
        for (int q = 0; q < 16; ++q) {
            int flat = t + q*256;
            int c4 = flat & 15, m = (flat >> 4) & 31, h = flat >> 9;
            float4 v = *(const float4*)(Kb + (m0+m)*DM + h*DHEAD + c4*4);
            float* kt = KV + h*KVSLOT;
            kt[(c4*4+0)*33 + m] = v.x;
            kt[(c4*4+1)*33 + m] = v.y;
            kt[(c4*4+2)*33 + m] = v.z;
            kt[(c4*4+3)*33 + m] = v.w;
        }
        __syncthreads();

        float w[3][4][4];
        float zr[4][4];
#pragma unroll
        for (int i = 0; i < 4; ++i)
#pragma unroll
            for (int j = 0; j < 4; ++j) zr[i][j] = 0.f;

        // ---- scores pass A: heads g, g+4
#pragma unroll
        for (int hh = 0; hh < 2; ++hh) {
            int h = g + hh*4;
            score_head(Qt + h*DHEAD*32 + r0, KV + h*KVSLOT + c0, w[hh], zr);
        }
        __syncthreads();
        // ---- stage Kt heads 8..11 into slots 0..3
#pragma unroll
        for (int q = 0; q < 8; ++q) {
            int flat = t + q*256;
            int c4 = flat & 15, m = (flat >> 4) & 31, h = flat >> 9;  // 0..3
            float4 v = *(const float4*)(Kb + (m0+m)*DM + (h+8)*DHEAD + c4*4);
            float* kt = KV + h*KVSLOT;
            kt[(c4*4+0)*33 + m] = v.x;
            kt[(c4*4+1)*33 + m] = v.y;
            kt[(c4*4+2)*33 + m] = v.z;
            kt[(c4*4+3)*33 + m] = v.w;
        }
        __syncthreads();
        // ---- scores pass B: head g+8 (slot g)
        score_head(Qt + (g+8)*DHEAD*32 + r0, KV + g*KVSLOT + c0, w[2], zr);

        // ---- head-axis z reduction
#pragma unroll
        for (int i = 0; i < 4; ++i)
#pragma unroll
            for (int j = 0; j < 4; ++j)
                atomicAdd(&zb[(c0+j)*33 + (r0+i)], zr[i][j]);
        __syncthreads();

        // ---- normalize, write Wt; then stage V heads 0..7 (natural layout)
#pragma unroll
        for (int j = 0; j < 4; ++j)
#pragma unroll
            for (int i = 0; i < 4; ++i) {
                int idx = (c0+j)*33 + (r0+i);
                float inv = __fdividef(1.f, zb[idx]);
                Wt[(g  )*1056 + idx] = w[0][i][j]*inv;
                Wt[(g+4)*1056 + idx] = w[1][i][j]*inv;
                Wt[(g+8)*1056 + idx] = w[2][i][j]*inv;
            }
#pragma unroll
        for (int q = 0; q < 16; ++q) {
            int flat = t + q*256;
            int c4 = flat & 15, m = (flat >> 4) & 31, h = flat >> 9;
            float4 v = *(const float4*)(Vb + (m0+m)*DM + h*DHEAD + c4*4);
            *(float4*)(KV + h*KVSLOT + m*64 + c4*4) = v;
        }
        __syncthreads();

        // ---- O pass A: heads g, g+4
#pragma unroll
        for (int hh = 0; hh < 2; ++hh) {
            int h = g + hh*4;
            o_accum(Wt + h*1056 + r0, KV + h*KVSLOT + d0, o[hh]);
        }
        __syncthreads();
        // ---- stage V heads 8..11 into slots 0..3
#pragma unroll
        for (int q = 0; q < 8; ++q) {
            int flat = t + q*256;
            int c4 = flat & 15, m = (flat >> 4) & 31, h = flat >> 9;
            float4 v = *(const float4*)(Vb + (m0+m)*DM + (h+8)*DHEAD + c4*4);
            *(float4*)(KV + h*KVSLOT + m*64 + c4*4) = v;
        }
        __syncthreads();
        // ---- O pass B: head g+8 (slot g)
        o_accum(Wt + (g+8)*1056 + r0, KV + g*KVSLOT + d0, o[2]);
    }

    // ---- writeback C[b, n0+r, h*64 + d0 ..]
#pragma unroll
    for (int hh = 0; hh < 3; ++hh) {
        int h = (hh < 2) ? (g + hh*4) : (g + 8);
#pragma unroll
        for (int i = 0; i < 4; ++i) {
            float* Cp = g_C + (size_t)(b*SEQ + n0 + r0 + i)*DM + h*DHEAD + d0;
            float4 a, b4;
            a.x = o[hh][i][0]; a.y = o[hh][i][1]; a.z = o[hh][i][2]; a.w = o[hh][i][3];
            b4.x = o[hh][i][4]; b4.y = o[hh][i][5]; b4.z = o[hh][i][6]; b4.w = o[hh][i][7];
            *(float4*)Cp       = a;
            *(float4*)(Cp + 4) = b4;
        }
    }
}

// ---------------------------------------------------------------------------
extern "C" void kernel_launch(void* const* d_in, const int* in_sizes, int n_in,
                              void* d_out, int out_size)
{
    const float* x  = (const float*)d_in[0];
    const float* Wq = (const float*)d_in[1];
    const float* bq = (const float*)d_in[2];
    const float* Wk = (const float*)d_in[3];
    const float* bk = (const float*)d_in[4];
    const float* Wv = (const float*)d_in[5];
    const float* bv = (const float*)d_in[6];
    const float* Wo = (const float*)d_in[7];
    const float* bo = (const float*)d_in[8];
    float* out = (float*)d_out;

    float *C;
    cudaGetSymbolAddress((void**)&C, g_C);

    cudaFuncSetAttribute(attn_kernel,
                         cudaFuncAttributeMaxDynamicSharedMemorySize,
                         ATTN_SMEM_BYTES);

    dim3 g3(DM/128, MTOT/128, 3);   // (6, 64, 3)
    gemm_qkv<<<g3, 256>>>(x, Wq, bq, Wk, bk, Wv, bv);

    attn_kernel<<<dim3(SEQ/32, BATCH), 256, ATTN_SMEM_BYTES>>>();

    dim3 gg(DM/128, MTOT/128);      // (6, 64)
    gemm_single<<<gg, 256>>>(C, Wo, bo, out);
}

// round 4
// speedup vs baseline: 2.6697x; 1.3519x over previous
#include <cuda_runtime.h>
#include <cstdint>

#define BATCH  8
#define SEQ    1024
#define DM     768
#define NHEAD  12
#define DHEAD  64
#define MTOT   (BATCH*SEQ)

// Scratch (device globals: no allocations allowed)
__device__ float g_Q[MTOT*DM];
__device__ float g_K[MTOT*DM];
__device__ float g_V[MTOT*DM];
__device__ float g_C[MTOT*DM];

// ===========================================================================
// tf32 mma.sync GEMM:  Y[M,768] = X[M,768] @ W[768,768]^T + bias
// Block tile 128(M) x 256(N), BK=16, 256 threads = 8 warps,
// warp tile 64x64 (warp grid 2m x 4n), mma.m16n8k8 tf32.
// smem: natural row-major, stride 20 floats (conflict-free fragment LDS).
// ===========================================================================
__device__ __forceinline__ uint32_t cvt_tf32(float f) {
    uint32_t r;
    asm("cvt.rna.tf32.f32 %0, %1;" : "=r"(r) : "f"(f));
    return r;
}

__device__ __forceinline__ void mma_tf32(float d[4], const uint32_t a[4],
                                         const uint32_t b[2]) {
    asm volatile(
        "mma.sync.aligned.m16n8k8.row.col.f32.tf32.tf32.f32 "
        "{%0,%1,%2,%3}, {%4,%5,%6,%7}, {%8,%9}, {%0,%1,%2,%3};"
        : "+f"(d[0]), "+f"(d[1]), "+f"(d[2]), "+f"(d[3])
        : "r"(a[0]), "r"(a[1]), "r"(a[2]), "r"(a[3]),
          "r"(b[0]), "r"(b[1]));
}

#define ASTRIDE 20
#define BSTRIDE 20

__device__ __forceinline__ void gemm_mma_body(
    const float* __restrict__ X, const float* __restrict__ W,
    const float* __restrict__ bias, float* __restrict__ Y,
    int bm, int bn)
{
    __shared__ float As[128*ASTRIDE];   // 10240 B
    __shared__ float Bs[256*BSTRIDE];   // 20480 B

    const int t    = threadIdx.x;
    const int wid  = t >> 5;
    const int lane = t & 31;
    const int g    = lane >> 2;     // 0..7
    const int tig  = lane & 3;      // 0..3
    const int wm   = wid >> 2;      // 0..1  -> m offset 64*wm
    const int wn   = wid & 3;       // 0..3  -> n offset 64*wn

    // global load mapping
    const int ar = t >> 2;          // A row 0..63 (and +64)
    const int ac = (t & 3) * 4;     // A col (floats)
    const float* Ag = X + (size_t)(bm + ar) * DM + ac;
    const float* Bg = W + (size_t)(bn + ar) * DM + ac;

    float acc[4][8][4];
#pragma unroll
    for (int mi = 0; mi < 4; ++mi)
#pragma unroll
        for (int ni = 0; ni < 8; ++ni)
#pragma unroll
            for (int q = 0; q < 4; ++q) acc[mi][ni][q] = 0.f;

    // prefetch chunk 0
    float4 pa[2], pb[4];
#pragma unroll
    for (int i = 0; i < 2; ++i) pa[i] = *(const float4*)(Ag + (size_t)i*64*DM);
#pragma unroll
    for (int i = 0; i < 4; ++i) pb[i] = *(const float4*)(Bg + (size_t)i*64*DM);

    const uint32_t* Asu = (const uint32_t*)As;
    const uint32_t* Bsu = (const uint32_t*)Bs;

    for (int c = 0; c < 48; ++c) {
        __syncthreads();
        // store (cvt to tf32)
#pragma unroll
        for (int i = 0; i < 2; ++i) {
            uint32_t* d = (uint32_t*)&As[(ar + i*64)*ASTRIDE + ac];
            d[0] = cvt_tf32(pa[i].x); d[1] = cvt_tf32(pa[i].y);
            d[2] = cvt_tf32(pa[i].z); d[3] = cvt_tf32(pa[i].w);
        }
#pragma unroll
        for (int i = 0; i < 4; ++i) {
            uint32_t* d = (uint32_t*)&Bs[(ar + i*64)*BSTRIDE + ac];
            d[0] = cvt_tf32(pb[i].x); d[1] = cvt_tf32(pb[i].y);
            d[2] = cvt_tf32(pb[i].z); d[3] = cvt_tf32(pb[i].w);
        }
        __syncthreads();

        if (c + 1 < 48) {
            const float* Agc = Ag + (c + 1) * 16;
            const float* Bgc = Bg + (c + 1) * 16;
#pragma unroll
            for (int i = 0; i < 2; ++i) pa[i] = *(const float4*)(Agc + (size_t)i*64*DM);
#pragma unroll
            for (int i = 0; i < 4; ++i) pb[i] = *(const float4*)(Bgc + (size_t)i*64*DM);
        }

#pragma unroll
        for (int kk = 0; kk < 16; kk += 8) {
            uint32_t a[4][4], b[8][2];
#pragma unroll
            for (int mi = 0; mi < 4; ++mi) {
                const uint32_t* ap = Asu + (wm*64 + mi*16 + g)*ASTRIDE + kk + tig;
                a[mi][0] = ap[0];
                a[mi][1] = ap[8*ASTRIDE];
                a[mi][2] = ap[4];
                a[mi][3] = ap[8*ASTRIDE + 4];
            }
#pragma unroll
            for (int ni = 0; ni < 8; ++ni) {
                const uint32_t* bp = Bsu + (wn*64 + ni*8 + g)*BSTRIDE + kk + tig;
                b[ni][0] = bp[0];
                b[ni][1] = bp[4];
            }
#pragma unroll
            for (int mi = 0; mi < 4; ++mi)
#pragma unroll
                for (int ni = 0; ni < 8; ++ni)
                    mma_tf32(acc[mi][ni], a[mi], b[ni]);
        }
    }

    // epilogue: c0,c1 -> (row g, cols 2tig..2tig+1); c2,c3 -> row g+8
#pragma unroll
    for (int mi = 0; mi < 4; ++mi) {
        const int row0 = bm + wm*64 + mi*16 + g;
#pragma unroll
        for (int ni = 0; ni < 8; ++ni) {
            const int col = bn + wn*64 + ni*8 + 2*tig;
            float2 bv = *(const float2*)(bias + col);
            float2 r0, r1;
            r0.x = acc[mi][ni][0] + bv.x;
            r0.y = acc[mi][ni][1] + bv.y;
            r1.x = acc[mi][ni][2] + bv.x;
            r1.y = acc[mi][ni][3] + bv.y;
            *(float2*)(Y + (size_t)row0 * DM + col)       = r0;
            *(float2*)(Y + (size_t)(row0 + 8) * DM + col) = r1;
        }
    }
}

__global__ __launch_bounds__(256) void gemm_mma_qkv(
    const float* __restrict__ X,
    const float* __restrict__ Wq, const float* __restrict__ bq,
    const float* __restrict__ Wk, const float* __restrict__ bk,
    const float* __restrict__ Wv, const float* __restrict__ bv)
{
    const float* W; const float* bb; float* Y;
    if (blockIdx.z == 0)      { W = Wq; bb = bq; Y = g_Q; }
    else if (blockIdx.z == 1) { W = Wk; bb = bk; Y = g_K; }
    else                      { W = Wv; bb = bv; Y = g_V; }
    gemm_mma_body(X, W, bb, Y, blockIdx.y * 128, blockIdx.x * 256);
}

__global__ __launch_bounds__(256) void gemm_mma_one(
    const float* __restrict__ X, const float* __restrict__ W,
    const float* __restrict__ bias, float* __restrict__ Y)
{
    gemm_mma_body(X, W, bias, Y, blockIdx.y * 128, blockIdx.x * 256);
}

// ===========================================================================
// Fused attention (unchanged, passing version): softmax over HEAD axis.
// ===========================================================================
#define QT_OFF 0
#define WT_OFF 24576
#define ZB_OFF 37248
#define KV_OFF 38304
#define KVSLOT 2112
#define SMEM_FLOATS 55200
#define ATTN_SMEM_BYTES (SMEM_FLOATS*4)

__device__ __forceinline__ void score_head(
    const float* __restrict__ qt, const float* __restrict__ kt,
    float w[4][4], float zr[4][4])
{
    float s[4][4];
#pragma unroll
    for (int i = 0; i < 4; ++i)
#pragma unroll
        for (int j = 0; j < 4; ++j) s[i][j] = 0.f;

#pragma unroll 8
    for (int d = 0; d < DHEAD; ++d) {
        float4 q4 = *(const float4*)(qt + d*32);
        float k0_ = kt[d*33 + 0];
        float k1_ = kt[d*33 + 1];
        float k2_ = kt[d*33 + 2];
        float k3_ = kt[d*33 + 3];
        s[0][0]+=q4.x*k0_; s[0][1]+=q4.x*k1_; s[0][2]+=q4.x*k2_; s[0][3]+=q4.x*k3_;
        s[1][0]+=q4.y*k0_; s[1][1]+=q4.y*k1_; s[1][2]+=q4.y*k2_; s[1][3]+=q4.y*k3_;
        s[2][0]+=q4.z*k0_; s[2][1]+=q4.z*k1_; s[2][2]+=q4.z*k2_; s[2][3]+=q4.z*k3_;
        s[3][0]+=q4.w*k0_; s[3][1]+=q4.w*k1_; s[3][2]+=q4.w*k2_; s[3][3]+=q4.w*k3_;
    }
#pragma unroll
    for (int i = 0; i < 4; ++i)
#pragma unroll
        for (int j = 0; j < 4; ++j) {
            float e = __expf(s[i][j]*0.125f);
            w[i][j] = e;
            zr[i][j] += e;
        }
}

__device__ __forceinline__ void o_accum(
    const float* __restrict__ wt, const float* __restrict__ vv, float o[4][8])
{
#pragma unroll 8
    for (int m = 0; m < 32; ++m) {
        float4 v0 = *(const float4*)(vv + m*64);
        float4 v1 = *(const float4*)(vv + m*64 + 4);
        float va[8] = {v0.x,v0.y,v0.z,v0.w,v1.x,v1.y,v1.z,v1.w};
#pragma unroll
        for (int i = 0; i < 4; ++i) {
            float wi = wt[m*33 + i];
#pragma unroll
            for (int k = 0; k < 8; ++k) o[i][k] += wi*va[k];
        }
    }
}

__global__ __launch_bounds__(256) void attn_kernel()
{
    extern __shared__ float smf[];
    float* Qt = smf + QT_OFF;
    float* Wt = smf + WT_OFF;
    float* zb = smf + ZB_OFF;
    float* KV = smf + KV_OFF;

    const int b  = blockIdx.y;
    const int n0 = blockIdx.x * 32;
    const int t  = threadIdx.x;
    const int g  = t >> 6;
    const int u  = t & 63;
    const int gr = u >> 3;
    const int gc = u & 7;
    const int r0 = gr*4, c0 = gc*4, d0 = gc*8;

    const float* Qb = g_Q + (size_t)(b*SEQ + n0)*DM;
    const float* Kb = g_K + (size_t)b*SEQ*DM;
    const float* Vb = g_V + (size_t)b*SEQ*DM;

    {
        const int rl = t & 31, cb = t >> 5;
#pragma unroll
        for (int q = 0; q < 24; ++q) {
            int cq = cb + q*8;
            float4 v = *(const float4*)(Qb + rl*DM + cq*4);
            Qt[(cq*4+0)*32 + rl] = v.x;
            Qt[(cq*4+1)*32 + rl] = v.y;
            Qt[(cq*4+2)*32 + rl] = v.z;
            Qt[(cq*4+3)*32 + rl] = v.w;
        }
    }

    float o[3][4][8];
#pragma unroll
    for (int hh = 0; hh < 3; ++hh)
#pragma unroll
        for (int i = 0; i < 4; ++i)
#pragma unroll
            for (int k = 0; k < 8; ++k) o[hh][i][k] = 0.f;

    for (int m0 = 0; m0 < SEQ; m0 += 32) {
        __syncthreads();
        for (int i = t; i < 1056; i += 256) zb[i] = 0.f;
#pragma unroll
        for (int q = 0; q < 16; ++q) {
            int flat = t + q*256;
            int cq = flat & 15, m = (flat >> 4) & 31, h = flat >> 9;
            float4 v = *(const float4*)(Kb + (m0+m)*DM + h*DHEAD + cq*4);
            float* kt = KV + h*KVSLOT;
            kt[(cq*4+0)*33 + m] = v.x;
            kt[(cq*4+1)*33 + m] = v.y;
            kt[(cq*4+2)*33 + m] = v.z;
            kt[(cq*4+3)*33 + m] = v.w;
        }
        __syncthreads();

        float w[3][4][4];
        float zr[4][4];
#pragma unroll
        for (int i = 0; i < 4; ++i)
#pragma unroll
            for (int j = 0; j < 4; ++j) zr[i][j] = 0.f;

#pragma unroll
        for (int hh = 0; hh < 2; ++hh) {
            int h = g + hh*4;
            score_head(Qt + h*DHEAD*32 + r0, KV + h*KVSLOT + c0, w[hh], zr);
        }
        __syncthreads();
#pragma unroll
        for (int q = 0; q < 8; ++q) {
            int flat = t + q*256;
            int cq = flat & 15, m = (flat >> 4) & 31, h = flat >> 9;
            float4 v = *(const float4*)(Kb + (m0+m)*DM + (h+8)*DHEAD + cq*4);
            float* kt = KV + h*KVSLOT;
            kt[(cq*4+0)*33 + m] = v.x;
            kt[(cq*4+1)*33 + m] = v.y;
            kt[(cq*4+2)*33 + m] = v.z;
            kt[(cq*4+3)*33 + m] = v.w;
        }
        __syncthreads();
        score_head(Qt + (g+8)*DHEAD*32 + r0, KV + g*KVSLOT + c0, w[2], zr);

#pragma unroll
        for (int i = 0; i < 4; ++i)
#pragma unroll
            for (int j = 0; j < 4; ++j)
                atomicAdd(&zb[(c0+j)*33 + (r0+i)], zr[i][j]);
        __syncthreads();

#pragma unroll
        for (int j = 0; j < 4; ++j)
#pragma unroll
            for (int i = 0; i < 4; ++i) {
                int idx = (c0+j)*33 + (r0+i);
                float inv = __fdividef(1.f, zb[idx]);
                Wt[(g  )*1056 + idx] = w[0][i][j]*inv;
                Wt[(g+4)*1056 + idx] = w[1][i][j]*inv;
                Wt[(g+8)*1056 + idx] = w[2][i][j]*inv;
            }
#pragma unroll
        for (int q = 0; q < 16; ++q) {
            int flat = t + q*256;
            int cq = flat & 15, m = (flat >> 4) & 31, h = flat >> 9;
            float4 v = *(const float4*)(Vb + (m0+m)*DM + h*DHEAD + cq*4);
            *(float4*)(KV + h*KVSLOT + m*64 + cq*4) = v;
        }
        __syncthreads();

#pragma unroll
        for (int hh = 0; hh < 2; ++hh) {
            int h = g + hh*4;
            o_accum(Wt + h*1056 + r0, KV + h*KVSLOT + d0, o[hh]);
        }
        __syncthreads();
#pragma unroll
        for (int q = 0; q < 8; ++q) {
            int flat = t + q*256;
            int cq = flat & 15, m = (flat >> 4) & 31, h = flat >> 9;
            float4 v = *(const float4*)(Vb + (m0+m)*DM + (h+8)*DHEAD + cq*4);
            *(float4*)(KV + h*KVSLOT + m*64 + cq*4) = v;
        }
        __syncthreads();
        o_accum(Wt + (g+8)*1056 + r0, KV + g*KVSLOT + d0, o[2]);
    }

#pragma unroll
    for (int hh = 0; hh < 3; ++hh) {
        int h = (hh < 2) ? (g + hh*4) : (g + 8);
#pragma unroll
        for (int i = 0; i < 4; ++i) {
            float* Cp = g_C + (size_t)(b*SEQ + n0 + r0 + i)*DM + h*DHEAD + d0;
            float4 a, b4;
            a.x = o[hh][i][0]; a.y = o[hh][i][1]; a.z = o[hh][i][2]; a.w = o[hh][i][3];
            b4.x = o[hh][i][4]; b4.y = o[hh][i][5]; b4.z = o[hh][i][6]; b4.w = o[hh][i][7];
            *(float4*)Cp       = a;
            *(float4*)(Cp + 4) = b4;
        }
    }
}

// ===========================================================================
extern "C" void kernel_launch(void* const* d_in, const int* in_sizes, int n_in,
                              void* d_out, int out_size)
{
    const float* x  = (const float*)d_in[0];
    const float* Wq = (const float*)d_in[1];
    const float* bq = (const float*)d_in[2];
    const float* Wk = (const float*)d_in[3];
    const float* bk = (const float*)d_in[4];
    const float* Wv = (const float*)d_in[5];
    const float* bv = (const float*)d_in[6];
    const float* Wo = (const float*)d_in[7];
    const float* bo = (const float*)d_in[8];
    float* out = (float*)d_out;

    float* C;
    cudaGetSymbolAddress((void**)&C, g_C);

    cudaFuncSetAttribute(attn_kernel,
                         cudaFuncAttributeMaxDynamicSharedMemorySize,
                         ATTN_SMEM_BYTES);

    dim3 g3(DM/256, MTOT/128, 3);   // (3, 64, 3)
    gemm_mma_qkv<<<g3, 256>>>(x, Wq, bq, Wk, bk, Wv, bv);

    attn_kernel<<<dim3(SEQ/32, BATCH), 256, ATTN_SMEM_BYTES>>>();

    dim3 gg(DM/256, MTOT/128);      // (3, 64)
    gemm_mma_one<<<gg, 256>>>(C, Wo, bo, out);
}

// round 5
// speedup vs baseline: 4.2283x; 1.5838x over previous
#include <cuda_runtime.h>
#include <cstdint>

#define BATCH  8
#define SEQ    1024
#define DM     768
#define NHEAD  12
#define DHEAD  64
#define MTOT   (BATCH*SEQ)

// Scratch (device globals: no allocations allowed)
__device__ float g_Q[MTOT*DM];
__device__ float g_K[MTOT*DM];
__device__ float g_V[MTOT*DM];
__device__ float g_C[MTOT*DM];

// ===========================================================================
// common mma helpers
// ===========================================================================
__device__ __forceinline__ uint32_t cvt_tf32(float f) {
    uint32_t r;
    asm("cvt.rna.tf32.f32 %0, %1;" : "=r"(r) : "f"(f));
    return r;
}

__device__ __forceinline__ void mma_tf32(float d[4], const uint32_t a[4],
                                         const uint32_t b[2]) {
    asm volatile(
        "mma.sync.aligned.m16n8k8.row.col.f32.tf32.tf32.f32 "
        "{%0,%1,%2,%3}, {%4,%5,%6,%7}, {%8,%9}, {%0,%1,%2,%3};"
        : "+f"(d[0]), "+f"(d[1]), "+f"(d[2]), "+f"(d[3])
        : "r"(a[0]), "r"(a[1]), "r"(a[2]), "r"(a[3]),
          "r"(b[0]), "r"(b[1]));
}

// ===========================================================================
// tf32 mma.sync GEMM:  Y[M,768] = X[M,768] @ W[768,768]^T + bias
// (unchanged from passing round-4 kernel)
// ===========================================================================
#define ASTRIDE 20
#define BSTRIDE 20

__device__ __forceinline__ void gemm_mma_body(
    const float* __restrict__ X, const float* __restrict__ W,
    const float* __restrict__ bias, float* __restrict__ Y,
    int bm, int bn)
{
    __shared__ float As[128*ASTRIDE];
    __shared__ float Bs[256*BSTRIDE];

    const int t    = threadIdx.x;
    const int wid  = t >> 5;
    const int lane = t & 31;
    const int g    = lane >> 2;
    const int tig  = lane & 3;
    const int wm   = wid >> 2;
    const int wn   = wid & 3;

    const int ar = t >> 2;
    const int ac = (t & 3) * 4;
    const float* Ag = X + (size_t)(bm + ar) * DM + ac;
    const float* Bg = W + (size_t)(bn + ar) * DM + ac;

    float acc[4][8][4];
#pragma unroll
    for (int mi = 0; mi < 4; ++mi)
#pragma unroll
        for (int ni = 0; ni < 8; ++ni)
#pragma unroll
            for (int q = 0; q < 4; ++q) acc[mi][ni][q] = 0.f;

    float4 pa[2], pb[4];
#pragma unroll
    for (int i = 0; i < 2; ++i) pa[i] = *(const float4*)(Ag + (size_t)i*64*DM);
#pragma unroll
    for (int i = 0; i < 4; ++i) pb[i] = *(const float4*)(Bg + (size_t)i*64*DM);

    const uint32_t* Asu = (const uint32_t*)As;
    const uint32_t* Bsu = (const uint32_t*)Bs;

    for (int c = 0; c < 48; ++c) {
        __syncthreads();
#pragma unroll
        for (int i = 0; i < 2; ++i) {
            uint32_t* d = (uint32_t*)&As[(ar + i*64)*ASTRIDE + ac];
            d[0] = cvt_tf32(pa[i].x); d[1] = cvt_tf32(pa[i].y);
            d[2] = cvt_tf32(pa[i].z); d[3] = cvt_tf32(pa[i].w);
        }
#pragma unroll
        for (int i = 0; i < 4; ++i) {
            uint32_t* d = (uint32_t*)&Bs[(ar + i*64)*BSTRIDE + ac];
            d[0] = cvt_tf32(pb[i].x); d[1] = cvt_tf32(pb[i].y);
            d[2] = cvt_tf32(pb[i].z); d[3] = cvt_tf32(pb[i].w);
        }
        __syncthreads();

        if (c + 1 < 48) {
            const float* Agc = Ag + (c + 1) * 16;
            const float* Bgc = Bg + (c + 1) * 16;
#pragma unroll
            for (int i = 0; i < 2; ++i) pa[i] = *(const float4*)(Agc + (size_t)i*64*DM);
#pragma unroll
            for (int i = 0; i < 4; ++i) pb[i] = *(const float4*)(Bgc + (size_t)i*64*DM);
        }

#pragma unroll
        for (int kk = 0; kk < 16; kk += 8) {
            uint32_t a[4][4], b[8][2];
#pragma unroll
            for (int mi = 0; mi < 4; ++mi) {
                const uint32_t* ap = Asu + (wm*64 + mi*16 + g)*ASTRIDE + kk + tig;
                a[mi][0] = ap[0];
                a[mi][1] = ap[8*ASTRIDE];
                a[mi][2] = ap[4];
                a[mi][3] = ap[8*ASTRIDE + 4];
            }
#pragma unroll
            for (int ni = 0; ni < 8; ++ni) {
                const uint32_t* bp = Bsu + (wn*64 + ni*8 + g)*BSTRIDE + kk + tig;
                b[ni][0] = bp[0];
                b[ni][1] = bp[4];
            }
#pragma unroll
            for (int mi = 0; mi < 4; ++mi)
#pragma unroll
                for (int ni = 0; ni < 8; ++ni)
                    mma_tf32(acc[mi][ni], a[mi], b[ni]);
        }
    }

#pragma unroll
    for (int mi = 0; mi < 4; ++mi) {
        const int row0 = bm + wm*64 + mi*16 + g;
#pragma unroll
        for (int ni = 0; ni < 8; ++ni) {
            const int col = bn + wn*64 + ni*8 + 2*tig;
            float2 bv = *(const float2*)(bias + col);
            float2 r0, r1;
            r0.x = acc[mi][ni][0] + bv.x;
            r0.y = acc[mi][ni][1] + bv.y;
            r1.x = acc[mi][ni][2] + bv.x;
            r1.y = acc[mi][ni][3] + bv.y;
            *(float2*)(Y + (size_t)row0 * DM + col)       = r0;
            *(float2*)(Y + (size_t)(row0 + 8) * DM + col) = r1;
        }
    }
}

__global__ __launch_bounds__(256) void gemm_mma_qkv(
    const float* __restrict__ X,
    const float* __restrict__ Wq, const float* __restrict__ bq,
    const float* __restrict__ Wk, const float* __restrict__ bk,
    const float* __restrict__ Wv, const float* __restrict__ bv)
{
    const float* W; const float* bb; float* Y;
    if (blockIdx.z == 0)      { W = Wq; bb = bq; Y = g_Q; }
    else if (blockIdx.z == 1) { W = Wk; bb = bk; Y = g_K; }
    else                      { W = Wv; bb = bv; Y = g_V; }
    gemm_mma_body(X, W, bb, Y, blockIdx.y * 128, blockIdx.x * 256);
}

__global__ __launch_bounds__(256) void gemm_mma_one(
    const float* __restrict__ X, const float* __restrict__ W,
    const float* __restrict__ bias, float* __restrict__ Y)
{
    gemm_mma_body(X, W, bias, Y, blockIdx.y * 128, blockIdx.x * 256);
}

// ===========================================================================
// tf32 mma attention, softmax over HEAD axis (local per (n,m)).
// Block = (batch, 32 n-rows). 8 warps = 4 groups x 2 n-halves.
// Group grp owns heads {grp, grp+4, grp+8}; warp handles 16 n-rows.
// K/V staged in 3 passes of 4 heads per 32-m tile.
// smem strides chosen for conflict-free fragment LDS:
//   Qs 772 (=4 mod 32), Ks 260 (=4), Vs 264 (=8), Wb 36 (=4), zb 33.
// ===========================================================================
#define QS_OFF 0
#define KS_OFF 24704
#define VS_OFF 33024
#define WB_OFF 41472
#define ZB_OFF 55296
#define ATTN_SMEM_FLOATS 56352
#define ATTN_SMEM_BYTES (ATTN_SMEM_FLOATS*4)

__global__ __launch_bounds__(256) void attn_mma_kernel()
{
    extern __shared__ float smf[];
    float* Qs = smf + QS_OFF;   // [32][772]
    float* Ks = smf + KS_OFF;   // [32][260]  (4 head slots x 64)
    float* Vs = smf + VS_OFF;   // [32][264]
    float* Wb = smf + WB_OFF;   // [12][32][36]
    float* zb = smf + ZB_OFF;   // [32][33]

    const int b   = blockIdx.y;
    const int n0  = blockIdx.x * 32;
    const int t   = threadIdx.x;
    const int wid = t >> 5, lane = t & 31;
    const int grp = wid >> 1, nh = wid & 1;
    const int g   = lane >> 2, tig = lane & 3;
    const int nb  = nh * 16;

    const float* Qg = g_Q + (size_t)(b*SEQ + n0)*DM;
    const float* Kg = g_K + (size_t)b*SEQ*DM;
    const float* Vg = g_V + (size_t)b*SEQ*DM;

    // ---- stage Q once (tf32) : row r = t>>3, 8 threads/row, 24 f4 each
    {
        const int qr = t >> 3, qc = t & 7;
        const float* src = Qg + (size_t)qr * DM + qc * 4;
        uint32_t* dst = (uint32_t*)(Qs + qr * 772 + qc * 4);
#pragma unroll
        for (int i = 0; i < 24; ++i) {
            float4 v = *(const float4*)(src + i * 32);
            dst[i*32+0]=cvt_tf32(v.x); dst[i*32+1]=cvt_tf32(v.y);
            dst[i*32+2]=cvt_tf32(v.z); dst[i*32+3]=cvt_tf32(v.w);
        }
    }

    float o[3][8][4];
#pragma unroll
    for (int p = 0; p < 3; ++p)
#pragma unroll
        for (int j = 0; j < 8; ++j)
#pragma unroll
            for (int q = 0; q < 4; ++q) o[p][j][q] = 0.f;

    // staging index decomposition (2048 f4 per 4-head pass)
    const int sc4 = t & 15;            // 16 f4 per 64-float head-row
    const int sm_ = (t >> 4) & 31;     // hmm only 16 values from t; combine with i
    // we use flat = t + i*256: c4 = flat&15, m = (flat>>4)&31, slot = flat>>9

    for (int m0 = 0; m0 < SEQ; m0 += 32) {
        // zero zb (safe: zb only read via invz regs before last syncs of prev tile)
        for (int i = t; i < 1056; i += 256) zb[i] = 0.f;

        float wsum[4][4];
#pragma unroll
        for (int j = 0; j < 4; ++j)
#pragma unroll
            for (int q = 0; q < 4; ++q) wsum[j][q] = 0.f;

        // ================= score passes =================
#pragma unroll
        for (int p = 0; p < 3; ++p) {
            __syncthreads();
            // stage K heads 4p..4p+3 (tf32), layout Ks[m][slot*64+d], stride 260
#pragma unroll
            for (int i = 0; i < 8; ++i) {
                int flat = t + i*256;
                int c4 = flat & 15, m = (flat >> 4) & 31, slot = flat >> 9;
                float4 v = *(const float4*)(Kg + (size_t)(m0+m)*DM + (4*p+slot)*64 + c4*4);
                uint32_t* d = (uint32_t*)(Ks + m*260 + slot*64 + c4*4);
                d[0]=cvt_tf32(v.x); d[1]=cvt_tf32(v.y); d[2]=cvt_tf32(v.z); d[3]=cvt_tf32(v.w);
            }
            __syncthreads();

            const int h = grp + 4*p;
            float s[4][4];
#pragma unroll
            for (int j = 0; j < 4; ++j)
#pragma unroll
                for (int q = 0; q < 4; ++q) s[j][q] = 0.f;

            const uint32_t* qa = (const uint32_t*)(Qs + (nb+g)*772 + h*64 + tig);
            const uint32_t* kb = (const uint32_t*)(Ks + g*260 + grp*64 + tig);
#pragma unroll
            for (int kk = 0; kk < 8; ++kk) {
                uint32_t a[4];
                a[0] = qa[kk*8];
                a[1] = qa[kk*8 + 8*772];
                a[2] = qa[kk*8 + 4];
                a[3] = qa[kk*8 + 4 + 8*772];
#pragma unroll
                for (int j = 0; j < 4; ++j) {
                    uint32_t bb[2];
                    bb[0] = kb[kk*8 + j*8*260];
                    bb[1] = kb[kk*8 + 4 + j*8*260];
                    mma_tf32(s[j], a, bb);
                }
            }
            // exp + accumulate head-sum + store raw weights
            float* wp0 = Wb + h*1152 + (nb+g)*36 + 2*tig;
#pragma unroll
            for (int j = 0; j < 4; ++j) {
                float e0 = __expf(s[j][0]*0.125f);
                float e1 = __expf(s[j][1]*0.125f);
                float e2 = __expf(s[j][2]*0.125f);
                float e3 = __expf(s[j][3]*0.125f);
                wsum[j][0]+=e0; wsum[j][1]+=e1; wsum[j][2]+=e2; wsum[j][3]+=e3;
                *(float2*)(wp0 + j*8)        = make_float2(e0, e1);
                *(float2*)(wp0 + j*8 + 8*36) = make_float2(e2, e3);
            }
        }

        // head-axis z reduction (4 groups hit each coord)
        {
            float* zlo = zb + (nb+g)*33 + 2*tig;
            float* zhi = zb + (nb+g+8)*33 + 2*tig;
#pragma unroll
            for (int j = 0; j < 4; ++j) {
                atomicAdd(zlo + j*8,     wsum[j][0]);
                atomicAdd(zlo + j*8 + 1, wsum[j][1]);
                atomicAdd(zhi + j*8,     wsum[j][2]);
                atomicAdd(zhi + j*8 + 1, wsum[j][3]);
            }
        }
        __syncthreads();

        // invz at AV a-frag coords: rows nb+g, nb+g+8; cols kk*8+tig, +4
        float iz[2][4][2];
        {
            const float* zlo = zb + (nb+g)*33;
            const float* zhi = zb + (nb+g+8)*33;
#pragma unroll
            for (int kk = 0; kk < 4; ++kk) {
                iz[0][kk][0] = __fdividef(1.f, zlo[kk*8+tig]);
                iz[0][kk][1] = __fdividef(1.f, zlo[kk*8+tig+4]);
                iz[1][kk][0] = __fdividef(1.f, zhi[kk*8+tig]);
                iz[1][kk][1] = __fdividef(1.f, zhi[kk*8+tig+4]);
            }
        }

        // ================= AV passes =================
#pragma unroll
        for (int p = 0; p < 3; ++p) {
            __syncthreads();
            // stage V heads 4p..4p+3 (tf32), layout Vs[m][slot*64+d], stride 264
#pragma unroll
            for (int i = 0; i < 8; ++i) {
                int flat = t + i*256;
                int c4 = flat & 15, m = (flat >> 4) & 31, slot = flat >> 9;
                float4 v = *(const float4*)(Vg + (size_t)(m0+m)*DM + (4*p+slot)*64 + c4*4);
                uint32_t* d = (uint32_t*)(Vs + m*264 + slot*64 + c4*4);
                d[0]=cvt_tf32(v.x); d[1]=cvt_tf32(v.y); d[2]=cvt_tf32(v.z); d[3]=cvt_tf32(v.w);
            }
            __syncthreads();

            const int h = grp + 4*p;
            const float* wa = Wb + h*1152 + (nb+g)*36 + tig;
            const uint32_t* vb = (const uint32_t*)(Vs + tig*264 + grp*64 + g);
#pragma unroll
            for (int kk = 0; kk < 4; ++kk) {
                uint32_t a[4];
                a[0] = cvt_tf32(wa[kk*8]          * iz[0][kk][0]);
                a[1] = cvt_tf32(wa[kk*8 + 8*36]   * iz[1][kk][0]);
                a[2] = cvt_tf32(wa[kk*8 + 4]      * iz[0][kk][1]);
                a[3] = cvt_tf32(wa[kk*8+4 + 8*36] * iz[1][kk][1]);
#pragma unroll
                for (int j = 0; j < 8; ++j) {
                    uint32_t bb[2];
                    bb[0] = vb[kk*8*264 + j*8];
                    bb[1] = vb[(kk*8+4)*264 + j*8];
                    mma_tf32(o[p][j], a, bb);
                }
            }
        }
    }

    // ---- writeback
#pragma unroll
    for (int p = 0; p < 3; ++p) {
        const int h = grp + 4*p;
        float* Cp = g_C + (size_t)(b*SEQ + n0 + nb + g)*DM + h*64 + 2*tig;
#pragma unroll
        for (int j = 0; j < 8; ++j) {
            *(float2*)(Cp + j*8)          = make_float2(o[p][j][0], o[p][j][1]);
            *(float2*)(Cp + 8*DM + j*8)   = make_float2(o[p][j][2], o[p][j][3]);
        }
    }
}

// ===========================================================================
extern "C" void kernel_launch(void* const* d_in, const int* in_sizes, int n_in,
                              void* d_out, int out_size)
{
    const float* x  = (const float*)d_in[0];
    const float* Wq = (const float*)d_in[1];
    const float* bq = (const float*)d_in[2];
    const float* Wk = (const float*)d_in[3];
    const float* bk = (const float*)d_in[4];
    const float* Wv = (const float*)d_in[5];
    const float* bv = (const float*)d_in[6];
    const float* Wo = (const float*)d_in[7];
    const float* bo = (const float*)d_in[8];
    float* out = (float*)d_out;

    float* C;
    cudaGetSymbolAddress((void**)&C, g_C);

    cudaFuncSetAttribute(attn_mma_kernel,
                         cudaFuncAttributeMaxDynamicSharedMemorySize,
                         ATTN_SMEM_BYTES);

    dim3 g3(DM/256, MTOT/128, 3);   // (3, 64, 3)
    gemm_mma_qkv<<<g3, 256>>>(x, Wq, bq, Wk, bk, Wv, bv);

    attn_mma_kernel<<<dim3(SEQ/32, BATCH), 256, ATTN_SMEM_BYTES>>>();

    dim3 gg(DM/256, MTOT/128);      // (3, 64)
    gemm_mma_one<<<gg, 256>>>(C, Wo, bo, out);
}

// round 6
// speedup vs baseline: 4.4392x; 1.0499x over previous
#include <cuda_runtime.h>
#include <cstdint>

#define BATCH  8
#define SEQ    1024
#define DM     768
#define NHEAD  12
#define DHEAD  64
#define MTOT   (BATCH*SEQ)

// Scratch (device globals: no allocations allowed)
__device__ float g_Q[MTOT*DM];
__device__ float g_K[MTOT*DM];
__device__ float g_V[MTOT*DM];
__device__ float g_C[MTOT*DM];

// ===========================================================================
// common mma helpers
// ===========================================================================
__device__ __forceinline__ uint32_t cvt_tf32(float f) {
    uint32_t r;
    asm("cvt.rna.tf32.f32 %0, %1;" : "=r"(r) : "f"(f));
    return r;
}

__device__ __forceinline__ void mma_tf32(float d[4], const uint32_t a[4],
                                         const uint32_t b[2]) {
    asm volatile(
        "mma.sync.aligned.m16n8k8.row.col.f32.tf32.tf32.f32 "
        "{%0,%1,%2,%3}, {%4,%5,%6,%7}, {%8,%9}, {%0,%1,%2,%3};"
        : "+f"(d[0]), "+f"(d[1]), "+f"(d[2]), "+f"(d[3])
        : "r"(a[0]), "r"(a[1]), "r"(a[2]), "r"(a[3]),
          "r"(b[0]), "r"(b[1]));
}

// ===========================================================================
// tf32 mma.sync GEMM:  Y[M,768] = X[M,768] @ W[768,768]^T + bias
// Block tile 128x256, BK=16, 8 warps, warp tile 64x64.
// DOUBLE-BUFFERED smem, single __syncthreads per K-chunk.
// smem layout (dynamic): As0[2560] As1[2560] Bs0[5120] Bs1[5120] floats.
// ===========================================================================
#define ASTRIDE 20
#define BSTRIDE 20
#define GEMM_SMEM_BYTES (15360*4)

__device__ __forceinline__ void gemm_stage(
    float* __restrict__ As, float* __restrict__ Bs, int ar, int ac,
    const float4 pa[2], const float4 pb[4])
{
#pragma unroll
    for (int i = 0; i < 2; ++i) {
        uint32_t* d = (uint32_t*)&As[(ar + i*64)*ASTRIDE + ac];
        d[0] = cvt_tf32(pa[i].x); d[1] = cvt_tf32(pa[i].y);
        d[2] = cvt_tf32(pa[i].z); d[3] = cvt_tf32(pa[i].w);
    }
#pragma unroll
    for (int i = 0; i < 4; ++i) {
        uint32_t* d = (uint32_t*)&Bs[(ar + i*64)*BSTRIDE + ac];
        d[0] = cvt_tf32(pb[i].x); d[1] = cvt_tf32(pb[i].y);
        d[2] = cvt_tf32(pb[i].z); d[3] = cvt_tf32(pb[i].w);
    }
}

__device__ __forceinline__ void gemm_mma_body(
    const float* __restrict__ X, const float* __restrict__ W,
    const float* __restrict__ bias, float* __restrict__ Y,
    int bm, int bn, float* __restrict__ sm)
{
    const int t    = threadIdx.x;
    const int wid  = t >> 5;
    const int lane = t & 31;
    const int g    = lane >> 2;
    const int tig  = lane & 3;
    const int wm   = wid >> 2;
    const int wn   = wid & 3;

    const int ar = t >> 2;
    const int ac = (t & 3) * 4;
    const float* Ag = X + (size_t)(bm + ar) * DM + ac;
    const float* Bg = W + (size_t)(bn + ar) * DM + ac;

    float acc[4][8][4];
#pragma unroll
    for (int mi = 0; mi < 4; ++mi)
#pragma unroll
        for (int ni = 0; ni < 8; ++ni)
#pragma unroll
            for (int q = 0; q < 4; ++q) acc[mi][ni][q] = 0.f;

    float4 pa[2], pb[4];
#pragma unroll
    for (int i = 0; i < 2; ++i) pa[i] = *(const float4*)(Ag + (size_t)i*64*DM);
#pragma unroll
    for (int i = 0; i < 4; ++i) pb[i] = *(const float4*)(Bg + (size_t)i*64*DM);

    gemm_stage(sm, sm + 5120, ar, ac, pa, pb);
    __syncthreads();

    for (int c = 0; c < 48; ++c) {
        if (c + 1 < 48) {
            const float* Agc = Ag + (c + 1) * 16;
            const float* Bgc = Bg + (c + 1) * 16;
#pragma unroll
            for (int i = 0; i < 2; ++i) pa[i] = *(const float4*)(Agc + (size_t)i*64*DM);
#pragma unroll
            for (int i = 0; i < 4; ++i) pb[i] = *(const float4*)(Bgc + (size_t)i*64*DM);
        }

        const uint32_t* Asu = (const uint32_t*)(sm + (c & 1) * 2560);
        const uint32_t* Bsu = (const uint32_t*)(sm + 5120 + (c & 1) * 5120);

#pragma unroll
        for (int kk = 0; kk < 16; kk += 8) {
            uint32_t a[4][4], b[8][2];
#pragma unroll
            for (int mi = 0; mi < 4; ++mi) {
                const uint32_t* ap = Asu + (wm*64 + mi*16 + g)*ASTRIDE + kk + tig;
                a[mi][0] = ap[0];
                a[mi][1] = ap[8*ASTRIDE];
                a[mi][2] = ap[4];
                a[mi][3] = ap[8*ASTRIDE + 4];
            }
#pragma unroll
            for (int ni = 0; ni < 8; ++ni) {
                const uint32_t* bp = Bsu + (wn*64 + ni*8 + g)*BSTRIDE + kk + tig;
                b[ni][0] = bp[0];
                b[ni][1] = bp[4];
            }
#pragma unroll
            for (int mi = 0; mi < 4; ++mi)
#pragma unroll
                for (int ni = 0; ni < 8; ++ni)
                    mma_tf32(acc[mi][ni], a[mi], b[ni]);
        }

        if (c + 1 < 48) {
            gemm_stage(sm + ((c+1)&1)*2560, sm + 5120 + ((c+1)&1)*5120, ar, ac, pa, pb);
            __syncthreads();
        }
    }

#pragma unroll
    for (int mi = 0; mi < 4; ++mi) {
        const int row0 = bm + wm*64 + mi*16 + g;
#pragma unroll
        for (int ni = 0; ni < 8; ++ni) {
            const int col = bn + wn*64 + ni*8 + 2*tig;
            float2 bv = *(const float2*)(bias + col);
            float2 r0, r1;
            r0.x = acc[mi][ni][0] + bv.x;
            r0.y = acc[mi][ni][1] + bv.y;
            r1.x = acc[mi][ni][2] + bv.x;
            r1.y = acc[mi][ni][3] + bv.y;
            *(float2*)(Y + (size_t)row0 * DM + col)       = r0;
            *(float2*)(Y + (size_t)(row0 + 8) * DM + col) = r1;
        }
    }
}

__global__ __launch_bounds__(256) void gemm_mma_qkv(
    const float* __restrict__ X,
    const float* __restrict__ Wq, const float* __restrict__ bq,
    const float* __restrict__ Wk, const float* __restrict__ bk,
    const float* __restrict__ Wv, const float* __restrict__ bv)
{
    extern __shared__ float smg[];
    const float* W; const float* bb; float* Y;
    if (blockIdx.z == 0)      { W = Wq; bb = bq; Y = g_Q; }
    else if (blockIdx.z == 1) { W = Wk; bb = bk; Y = g_K; }
    else                      { W = Wv; bb = bv; Y = g_V; }
    gemm_mma_body(X, W, bb, Y, blockIdx.y * 128, blockIdx.x * 256, smg);
}

__global__ __launch_bounds__(256) void gemm_mma_one(
    const float* __restrict__ X, const float* __restrict__ W,
    const float* __restrict__ bias, float* __restrict__ Y)
{
    extern __shared__ float smg[];
    gemm_mma_body(X, W, bias, Y, blockIdx.y * 128, blockIdx.x * 256, smg);
}

// ===========================================================================
// tf32 mma attention v2, softmax over HEAD axis (local per (n,m)).
// Block = (batch, 32 n-rows). 8 warps = 4 groups x 2 n-halves.
// ALL 12 heads of K (then V) staged per 32-m tile -> 4 syncthreads per tile.
// Score->AV fragment layout conversion via warp shuffles (no Wb smem).
// smem: Qs[32][772] tf32, KVs (stride 772 for K / 776 for V), zb[32][33].
// ===========================================================================
#define AQ_STR 772
#define AK_STR 772
#define AV_STR 776
#define KV_OFF 24704
#define ZB_OFF (24704 + 24832)
#define ATTN_SMEM_FLOATS (24704 + 24832 + 1056)
#define ATTN_SMEM_BYTES (ATTN_SMEM_FLOATS*4)

__global__ __launch_bounds__(256) void attn_mma_kernel()
{
    extern __shared__ float smf[];
    float* Qs  = smf;              // [32][772]
    float* KVs = smf + KV_OFF;     // [32][772 or 776]
    float* zb  = smf + ZB_OFF;     // [32][33]

    const int b   = blockIdx.y;
    const int n0  = blockIdx.x * 32;
    const int t   = threadIdx.x;
    const int wid = t >> 5, lane = t & 31;
    const int grp = wid >> 1, nh = wid & 1;
    const int g   = lane >> 2, tig = lane & 3;
    const int nb  = nh * 16;

    const float* Qg = g_Q + (size_t)(b*SEQ + n0)*DM;
    const float* Kg = g_K + (size_t)b*SEQ*DM;
    const float* Vg = g_V + (size_t)b*SEQ*DM;

    // ---- stage Q once (tf32, stride 772): row t>>3, 8 threads/row
    {
        const int qr = t >> 3, qc = t & 7;
        const float* src = Qg + (size_t)qr * DM + qc * 4;
        uint32_t* dst = (uint32_t*)(Qs + qr * AQ_STR) + qc * 4;
#pragma unroll
        for (int i = 0; i < 24; ++i) {
            float4 v = *(const float4*)(src + i * 32);
            uint4 o4;
            o4.x = cvt_tf32(v.x); o4.y = cvt_tf32(v.y);
            o4.z = cvt_tf32(v.z); o4.w = cvt_tf32(v.w);
            *(uint4*)(dst + i*32) = o4;
        }
    }

    float o[3][8][4];
#pragma unroll
    for (int p = 0; p < 3; ++p)
#pragma unroll
        for (int j = 0; j < 8; ++j)
#pragma unroll
            for (int q = 0; q < 4; ++q) o[p][j][q] = 0.f;

    const int srow = t >> 3;           // staging row 0..31
    const int sc   = t & 7;            // staging f4 lane

    for (int m0 = 0; m0 < SEQ; m0 += 32) {
        __syncthreads();   // sync0: prev tile's KV reads + iz reads complete

        // zero zb + stage K (all 12 heads, tf32, stride 772)
        for (int i = t; i < 1056; i += 256) zb[i] = 0.f;
        {
            const float* ksrc = Kg + (size_t)(m0 + srow) * DM + sc * 4;
            uint32_t* kdst = (uint32_t*)(KVs + srow * AK_STR) + sc * 4;
#pragma unroll
            for (int i = 0; i < 24; ++i) {
                float4 v = *(const float4*)(ksrc + i * 32);
                uint4 o4;
                o4.x = cvt_tf32(v.x); o4.y = cvt_tf32(v.y);
                o4.z = cvt_tf32(v.z); o4.w = cvt_tf32(v.w);
                *(uint4*)(kdst + i*32) = o4;
            }
        }
        __syncthreads();   // sync1: K staged

        // ---- scores: 3 heads, uninterrupted mma burst
        float w[3][4][4];
        float wsum[4][4];
#pragma unroll
        for (int j = 0; j < 4; ++j)
#pragma unroll
            for (int q = 0; q < 4; ++q) wsum[j][q] = 0.f;

#pragma unroll
        for (int p = 0; p < 3; ++p) {
            const int h = grp + 4*p;
            float s[4][4];
#pragma unroll
            for (int j = 0; j < 4; ++j)
#pragma unroll
                for (int q = 0; q < 4; ++q) s[j][q] = 0.f;

            const uint32_t* qa = (const uint32_t*)(Qs + (nb+g)*AQ_STR + h*64 + tig);
            const uint32_t* kb = (const uint32_t*)(KVs + g*AK_STR + h*64 + tig);
#pragma unroll
            for (int kk = 0; kk < 8; ++kk) {
                uint32_t a[4];
                a[0] = qa[kk*8];
                a[1] = qa[kk*8 + 8*AQ_STR];
                a[2] = qa[kk*8 + 4];
                a[3] = qa[kk*8 + 4 + 8*AQ_STR];
#pragma unroll
                for (int j = 0; j < 4; ++j) {
                    uint32_t bb[2];
                    bb[0] = kb[kk*8 + j*8*AK_STR];
                    bb[1] = kb[kk*8 + 4 + j*8*AK_STR];
                    mma_tf32(s[j], a, bb);
                }
            }
#pragma unroll
            for (int j = 0; j < 4; ++j) {
                float e0 = __expf(s[j][0]*0.125f);
                float e1 = __expf(s[j][1]*0.125f);
                float e2 = __expf(s[j][2]*0.125f);
                float e3 = __expf(s[j][3]*0.125f);
                w[p][j][0]=e0; w[p][j][1]=e1; w[p][j][2]=e2; w[p][j][3]=e3;
                wsum[j][0]+=e0; wsum[j][1]+=e1; wsum[j][2]+=e2; wsum[j][3]+=e3;
            }
        }

        // head-axis z reduction (4 groups per coord)
        {
            float* zlo = zb + (nb+g)*33 + 2*tig;
            float* zhi = zb + (nb+g+8)*33 + 2*tig;
#pragma unroll
            for (int j = 0; j < 4; ++j) {
                atomicAdd(zlo + j*8,     wsum[j][0]);
                atomicAdd(zlo + j*8 + 1, wsum[j][1]);
                atomicAdd(zhi + j*8,     wsum[j][2]);
                atomicAdd(zhi + j*8 + 1, wsum[j][3]);
            }
        }
        __syncthreads();   // sync2: z complete; scores (K reads) complete

        // invz at AV a-frag coords
        float iz[2][4][2];
        {
            const float* zlo = zb + (nb+g)*33;
            const float* zhi = zb + (nb+g+8)*33;
#pragma unroll
            for (int kk = 0; kk < 4; ++kk) {
                iz[0][kk][0] = __fdividef(1.f, zlo[kk*8+tig]);
                iz[0][kk][1] = __fdividef(1.f, zlo[kk*8+tig+4]);
                iz[1][kk][0] = __fdividef(1.f, zhi[kk*8+tig]);
                iz[1][kk][1] = __fdividef(1.f, zhi[kk*8+tig+4]);
            }
        }

        // stage V (all 12 heads, tf32, stride 776; overwrites K region)
        {
            const float* vsrc = Vg + (size_t)(m0 + srow) * DM + sc * 4;
            uint32_t* vdst = (uint32_t*)(KVs + srow * AV_STR) + sc * 4;
#pragma unroll
            for (int i = 0; i < 24; ++i) {
                float4 v = *(const float4*)(vsrc + i * 32);
                uint4 o4;
                o4.x = cvt_tf32(v.x); o4.y = cvt_tf32(v.y);
                o4.z = cvt_tf32(v.z); o4.w = cvt_tf32(v.w);
                *(uint4*)(vdst + i*32) = o4;
            }
        }
        __syncthreads();   // sync3: V staged

        // ---- AV: 3 heads, shuffle-built a-frags, uninterrupted burst
        const int srcA = 4*g + (tig >> 1);
        const bool odd = (tig & 1);
#pragma unroll
        for (int p = 0; p < 3; ++p) {
            const int h = grp + 4*p;
            const uint32_t* vb = (const uint32_t*)(KVs + tig*AV_STR + h*64 + g);
#pragma unroll
            for (int kk = 0; kk < 4; ++kk) {
                float v0 = __shfl_sync(0xffffffffu, w[p][kk][0], srcA);
                float v1 = __shfl_sync(0xffffffffu, w[p][kk][1], srcA);
                float v2 = __shfl_sync(0xffffffffu, w[p][kk][2], srcA);
                float v3 = __shfl_sync(0xffffffffu, w[p][kk][3], srcA);
                float u0 = __shfl_sync(0xffffffffu, w[p][kk][0], srcA + 2);
                float u1 = __shfl_sync(0xffffffffu, w[p][kk][1], srcA + 2);
                float u2 = __shfl_sync(0xffffffffu, w[p][kk][2], srcA + 2);
                float u3 = __shfl_sync(0xffffffffu, w[p][kk][3], srcA + 2);
                float w00 = odd ? v1 : v0;   // row nb+g,   col kk*8+tig
                float w10 = odd ? v3 : v2;   // row nb+g+8, col kk*8+tig
                float w01 = odd ? u1 : u0;   // row nb+g,   col kk*8+tig+4
                float w11 = odd ? u3 : u2;   // row nb+g+8, col kk*8+tig+4
                uint32_t a[4];
                a[0] = cvt_tf32(w00 * iz[0][kk][0]);
                a[1] = cvt_tf32(w10 * iz[1][kk][0]);
                a[2] = cvt_tf32(w01 * iz[0][kk][1]);
                a[3] = cvt_tf32(w11 * iz[1][kk][1]);
#pragma unroll
                for (int j = 0; j < 8; ++j) {
                    uint32_t bb[2];
                    bb[0] = vb[kk*8*AV_STR + j*8];
                    bb[1] = vb[(kk*8+4)*AV_STR + j*8];
                    mma_tf32(o[p][j], a, bb);
                }
            }
        }
    }

    // ---- writeback
#pragma unroll
    for (int p = 0; p < 3; ++p) {
        const int h = grp + 4*p;
        float* Cp = g_C + (size_t)(b*SEQ + n0 + nb + g)*DM + h*64 + 2*tig;
#pragma unroll
        for (int j = 0; j < 8; ++j) {
            *(float2*)(Cp + j*8)        = make_float2(o[p][j][0], o[p][j][1]);
            *(float2*)(Cp + 8*DM + j*8) = make_float2(o[p][j][2], o[p][j][3]);
        }
    }
}

// ===========================================================================
extern "C" void kernel_launch(void* const* d_in, const int* in_sizes, int n_in,
                              void* d_out, int out_size)
{
    const float* x  = (const float*)d_in[0];
    const float* Wq = (const float*)d_in[1];
    const float* bq = (const float*)d_in[2];
    const float* Wk = (const float*)d_in[3];
    const float* bk = (const float*)d_in[4];
    const float* Wv = (const float*)d_in[5];
    const float* bv = (const float*)d_in[6];
    const float* Wo = (const float*)d_in[7];
    const float* bo = (const float*)d_in[8];
    float* out = (float*)d_out;

    float* C;
    cudaGetSymbolAddress((void**)&C, g_C);

    cudaFuncSetAttribute(attn_mma_kernel,
                         cudaFuncAttributeMaxDynamicSharedMemorySize,
                         ATTN_SMEM_BYTES);
    cudaFuncSetAttribute(gemm_mma_qkv,
                         cudaFuncAttributeMaxDynamicSharedMemorySize,
                         GEMM_SMEM_BYTES);
    cudaFuncSetAttribute(gemm_mma_one,
                         cudaFuncAttributeMaxDynamicSharedMemorySize,
                         GEMM_SMEM_BYTES);

    dim3 g3(DM/256, MTOT/128, 3);   // (3, 64, 3)
    gemm_mma_qkv<<<g3, 256, GEMM_SMEM_BYTES>>>(x, Wq, bq, Wk, bk, Wv, bv);

    attn_mma_kernel<<<dim3(SEQ/32, BATCH), 256, ATTN_SMEM_BYTES>>>();

    dim3 gg(DM/256, MTOT/128);      // (3, 64)
    gemm_mma_one<<<gg, 256, GEMM_SMEM_BYTES>>>(C, Wo, bo, out);
}

// round 7
// speedup vs baseline: 4.6952x; 1.0577x over previous
#include <cuda_runtime.h>
#include <cstdint>

#define BATCH  8
#define SEQ    1024
#define DM     768
#define NHEAD  12
#define DHEAD  64
#define MTOT   (BATCH*SEQ)

// Scratch (device globals: no allocations allowed)
__device__ float g_Q[MTOT*DM];   // tf32-rounded bits
__device__ float g_K[MTOT*DM];   // tf32-rounded bits
__device__ float g_V[MTOT*DM];   // tf32-rounded bits
__device__ float g_C[MTOT*DM];   // fp32

// ===========================================================================
// common mma helpers
// ===========================================================================
__device__ __forceinline__ uint32_t cvt_tf32(float f) {
    uint32_t r;
    asm("cvt.rna.tf32.f32 %0, %1;" : "=r"(r) : "f"(f));
    return r;
}

__device__ __forceinline__ void mma_tf32(float d[4], const uint32_t a[4],
                                         const uint32_t b[2]) {
    asm volatile(
        "mma.sync.aligned.m16n8k8.row.col.f32.tf32.tf32.f32 "
        "{%0,%1,%2,%3}, {%4,%5,%6,%7}, {%8,%9}, {%0,%1,%2,%3};"
        : "+f"(d[0]), "+f"(d[1]), "+f"(d[2]), "+f"(d[3])
        : "r"(a[0]), "r"(a[1]), "r"(a[2]), "r"(a[3]),
          "r"(b[0]), "r"(b[1]));
}

// ===========================================================================
// tf32 mma.sync GEMM:  Y[M,768] = X[M,768] @ W[768,768]^T + bias
// Block tile 128x256, BK=16, 8 warps, warp tile 64x64.
// Pair-permuted smem layout: (k, k+4) adjacent -> all fragment loads LDS.64.
//   slot(k) = (k>>3)*8 + (k&3)*2 + ((k>>2)&1)
// ROUND: if true, output is tf32-rounded bits (for Q/K/V feeding attention).
// ===========================================================================
#define ASTRIDE 20
#define BSTRIDE 20

template<bool ROUND>
__device__ __forceinline__ void gemm_mma_body(
    const float* __restrict__ X, const float* __restrict__ W,
    const float* __restrict__ bias, float* __restrict__ Y,
    int bm, int bn)
{
    __shared__ float As[128*ASTRIDE];
    __shared__ float Bs[256*BSTRIDE];

    const int t    = threadIdx.x;
    const int wid  = t >> 5;
    const int lane = t & 31;
    const int g    = lane >> 2;
    const int tig  = lane & 3;
    const int wm   = wid >> 2;
    const int wn   = wid & 3;

    const int ar = t >> 2;
    const int ac = (t & 3) * 4;
    // pair-layout store base for this thread's 4 consecutive k values
    const int sbase = ((ac >> 3) << 3) | ((ac >> 2) & 1);   // {0,1,8,9}

    const float* Ag = X + (size_t)(bm + ar) * DM + ac;
    const float* Bg = W + (size_t)(bn + ar) * DM + ac;

    float acc[4][8][4];
#pragma unroll
    for (int mi = 0; mi < 4; ++mi)
#pragma unroll
        for (int ni = 0; ni < 8; ++ni)
#pragma unroll
            for (int q = 0; q < 4; ++q) acc[mi][ni][q] = 0.f;

    float4 pa[2], pb[4];
#pragma unroll
    for (int i = 0; i < 2; ++i) pa[i] = *(const float4*)(Ag + (size_t)i*64*DM);
#pragma unroll
    for (int i = 0; i < 4; ++i) pb[i] = *(const float4*)(Bg + (size_t)i*64*DM);

    const uint32_t* Asu = (const uint32_t*)As;
    const uint32_t* Bsu = (const uint32_t*)Bs;

    for (int c = 0; c < 48; ++c) {
        __syncthreads();
#pragma unroll
        for (int i = 0; i < 2; ++i) {
            uint32_t* d = (uint32_t*)&As[(ar + i*64)*ASTRIDE] + sbase;
            d[0] = cvt_tf32(pa[i].x); d[2] = cvt_tf32(pa[i].y);
            d[4] = cvt_tf32(pa[i].z); d[6] = cvt_tf32(pa[i].w);
        }
#pragma unroll
        for (int i = 0; i < 4; ++i) {
            uint32_t* d = (uint32_t*)&Bs[(ar + i*64)*BSTRIDE] + sbase;
            d[0] = cvt_tf32(pb[i].x); d[2] = cvt_tf32(pb[i].y);
            d[4] = cvt_tf32(pb[i].z); d[6] = cvt_tf32(pb[i].w);
        }
        __syncthreads();

        if (c + 1 < 48) {
            const float* Agc = Ag + (c + 1) * 16;
            const float* Bgc = Bg + (c + 1) * 16;
#pragma unroll
            for (int i = 0; i < 2; ++i) pa[i] = *(const float4*)(Agc + (size_t)i*64*DM);
#pragma unroll
            for (int i = 0; i < 4; ++i) pb[i] = *(const float4*)(Bgc + (size_t)i*64*DM);
        }

#pragma unroll
        for (int kk = 0; kk < 16; kk += 8) {
            uint32_t a[4][4], b[8][2];
#pragma unroll
            for (int mi = 0; mi < 4; ++mi) {
                const uint32_t* ap = Asu + (wm*64 + mi*16 + g)*ASTRIDE + kk + 2*tig;
                uint2 lo = *(const uint2*)ap;
                uint2 hi = *(const uint2*)(ap + 8*ASTRIDE);
                a[mi][0] = lo.x; a[mi][1] = hi.x; a[mi][2] = lo.y; a[mi][3] = hi.y;
            }
#pragma unroll
            for (int ni = 0; ni < 8; ++ni) {
                const uint32_t* bp = Bsu + (wn*64 + ni*8 + g)*BSTRIDE + kk + 2*tig;
                uint2 v = *(const uint2*)bp;
                b[ni][0] = v.x; b[ni][1] = v.y;
            }
#pragma unroll
            for (int mi = 0; mi < 4; ++mi)
#pragma unroll
                for (int ni = 0; ni < 8; ++ni)
                    mma_tf32(acc[mi][ni], a[mi], b[ni]);
        }
    }

#pragma unroll
    for (int mi = 0; mi < 4; ++mi) {
        const int row0 = bm + wm*64 + mi*16 + g;
#pragma unroll
        for (int ni = 0; ni < 8; ++ni) {
            const int col = bn + wn*64 + ni*8 + 2*tig;
            float2 bv = *(const float2*)(bias + col);
            float2 r0, r1;
            if (ROUND) {
                r0.x = __uint_as_float(cvt_tf32(acc[mi][ni][0] + bv.x));
                r0.y = __uint_as_float(cvt_tf32(acc[mi][ni][1] + bv.y));
                r1.x = __uint_as_float(cvt_tf32(acc[mi][ni][2] + bv.x));
                r1.y = __uint_as_float(cvt_tf32(acc[mi][ni][3] + bv.y));
            } else {
                r0.x = acc[mi][ni][0] + bv.x;
                r0.y = acc[mi][ni][1] + bv.y;
                r1.x = acc[mi][ni][2] + bv.x;
                r1.y = acc[mi][ni][3] + bv.y;
            }
            *(float2*)(Y + (size_t)row0 * DM + col)       = r0;
            *(float2*)(Y + (size_t)(row0 + 8) * DM + col) = r1;
        }
    }
}

__global__ __launch_bounds__(256) void gemm_mma_qkv(
    const float* __restrict__ X,
    const float* __restrict__ Wq, const float* __restrict__ bq,
    const float* __restrict__ Wk, const float* __restrict__ bk,
    const float* __restrict__ Wv, const float* __restrict__ bv)
{
    const float* W; const float* bb; float* Y;
    if (blockIdx.z == 0)      { W = Wq; bb = bq; Y = g_Q; }
    else if (blockIdx.z == 1) { W = Wk; bb = bk; Y = g_K; }
    else                      { W = Wv; bb = bv; Y = g_V; }
    gemm_mma_body<true>(X, W, bb, Y, blockIdx.y * 128, blockIdx.x * 256);
}

__global__ __launch_bounds__(256) void gemm_mma_one(
    const float* __restrict__ X, const float* __restrict__ W,
    const float* __restrict__ bias, float* __restrict__ Y)
{
    gemm_mma_body<false>(X, W, bias, Y, blockIdx.y * 128, blockIdx.x * 256);
}

// ===========================================================================
// tf32 mma attention, softmax over HEAD axis (local per (n,m)).
// Q/K/V arrive PRE-ROUNDED to tf32 -> staging is pure copy (no cvt).
// Block = (batch, 32 n-rows). 8 warps = 4 groups x 2 n-halves.
// 4 syncthreads per 32-m tile; score->AV layout conversion via shuffles.
// ===========================================================================
#define AQ_STR 772
#define AK_STR 772
#define AV_STR 776
#define KV_OFF 24704
#define ZB_OFF (24704 + 24832)
#define ATTN_SMEM_FLOATS (24704 + 24832 + 1056)
#define ATTN_SMEM_BYTES (ATTN_SMEM_FLOATS*4)

__global__ __launch_bounds__(256) void attn_mma_kernel()
{
    extern __shared__ float smf[];
    float* Qs  = smf;              // [32][772]
    float* KVs = smf + KV_OFF;     // [32][772 or 776]
    float* zb  = smf + ZB_OFF;     // [32][33]

    const int b   = blockIdx.y;
    const int n0  = blockIdx.x * 32;
    const int t   = threadIdx.x;
    const int wid = t >> 5, lane = t & 31;
    const int grp = wid >> 1, nh = wid & 1;
    const int g   = lane >> 2, tig = lane & 3;
    const int nb  = nh * 16;

    const float* Qg = g_Q + (size_t)(b*SEQ + n0)*DM;
    const float* Kg = g_K + (size_t)b*SEQ*DM;
    const float* Vg = g_V + (size_t)b*SEQ*DM;

    // ---- stage Q once (pure copy; already tf32)
    {
        const int qr = t >> 3, qc = t & 7;
        const uint4* src = (const uint4*)(Qg + (size_t)qr * DM) + qc;
        uint32_t* dst = (uint32_t*)(Qs + qr * AQ_STR) + qc * 4;
#pragma unroll
        for (int i = 0; i < 24; ++i)
            *(uint4*)(dst + i*32) = src[i*8];
    }

    float o[3][8][4];
#pragma unroll
    for (int p = 0; p < 3; ++p)
#pragma unroll
        for (int j = 0; j < 8; ++j)
#pragma unroll
            for (int q = 0; q < 4; ++q) o[p][j][q] = 0.f;

    const int srow = t >> 3;
    const int sc   = t & 7;

    for (int m0 = 0; m0 < SEQ; m0 += 32) {
        __syncthreads();   // sync0: prev tile's reads complete

        for (int i = t; i < 1056; i += 256) zb[i] = 0.f;
        {   // stage K (pure copy)
            const uint4* ksrc = (const uint4*)(Kg + (size_t)(m0 + srow) * DM) + sc;
            uint32_t* kdst = (uint32_t*)(KVs + srow * AK_STR) + sc * 4;
#pragma unroll
            for (int i = 0; i < 24; ++i)
                *(uint4*)(kdst + i*32) = ksrc[i*8];
        }
        __syncthreads();   // sync1: K staged

        // ---- scores: 3 heads, uninterrupted mma burst
        float w[3][4][4];
        float wsum[4][4];
#pragma unroll
        for (int j = 0; j < 4; ++j)
#pragma unroll
            for (int q = 0; q < 4; ++q) wsum[j][q] = 0.f;

#pragma unroll
        for (int p = 0; p < 3; ++p) {
            const int h = grp + 4*p;
            float s[4][4];
#pragma unroll
            for (int j = 0; j < 4; ++j)
#pragma unroll
                for (int q = 0; q < 4; ++q) s[j][q] = 0.f;

            const uint32_t* qa = (const uint32_t*)(Qs + (nb+g)*AQ_STR + h*64 + tig);
            const uint32_t* kb = (const uint32_t*)(KVs + g*AK_STR + h*64 + tig);
#pragma unroll
            for (int kk = 0; kk < 8; ++kk) {
                uint32_t a[4];
                a[0] = qa[kk*8];
                a[1] = qa[kk*8 + 8*AQ_STR];
                a[2] = qa[kk*8 + 4];
                a[3] = qa[kk*8 + 4 + 8*AQ_STR];
#pragma unroll
                for (int j = 0; j < 4; ++j) {
                    uint32_t bb[2];
                    bb[0] = kb[kk*8 + j*8*AK_STR];
                    bb[1] = kb[kk*8 + 4 + j*8*AK_STR];
                    mma_tf32(s[j], a, bb);
                }
            }
#pragma unroll
            for (int j = 0; j < 4; ++j) {
                float e0 = __expf(s[j][0]*0.125f);
                float e1 = __expf(s[j][1]*0.125f);
                float e2 = __expf(s[j][2]*0.125f);
                float e3 = __expf(s[j][3]*0.125f);
                w[p][j][0]=e0; w[p][j][1]=e1; w[p][j][2]=e2; w[p][j][3]=e3;
                wsum[j][0]+=e0; wsum[j][1]+=e1; wsum[j][2]+=e2; wsum[j][3]+=e3;
            }
        }

        // head-axis z reduction
        {
            float* zlo = zb + (nb+g)*33 + 2*tig;
            float* zhi = zb + (nb+g+8)*33 + 2*tig;
#pragma unroll
            for (int j = 0; j < 4; ++j) {
                atomicAdd(zlo + j*8,     wsum[j][0]);
                atomicAdd(zlo + j*8 + 1, wsum[j][1]);
                atomicAdd(zhi + j*8,     wsum[j][2]);
                atomicAdd(zhi + j*8 + 1, wsum[j][3]);
            }
        }
        __syncthreads();   // sync2: z complete; K reads complete

        float iz[2][4][2];
        {
            const float* zlo = zb + (nb+g)*33;
            const float* zhi = zb + (nb+g+8)*33;
#pragma unroll
            for (int kk = 0; kk < 4; ++kk) {
                iz[0][kk][0] = __fdividef(1.f, zlo[kk*8+tig]);
                iz[0][kk][1] = __fdividef(1.f, zlo[kk*8+tig+4]);
                iz[1][kk][0] = __fdividef(1.f, zhi[kk*8+tig]);
                iz[1][kk][1] = __fdividef(1.f, zhi[kk*8+tig+4]);
            }
        }

        {   // stage V (pure copy)
            const uint4* vsrc = (const uint4*)(Vg + (size_t)(m0 + srow) * DM) + sc;
            uint32_t* vdst = (uint32_t*)(KVs + srow * AV_STR) + sc * 4;
#pragma unroll
            for (int i = 0; i < 24; ++i)
                *(uint4*)(vdst + i*32) = vsrc[i*8];
        }
        __syncthreads();   // sync3: V staged

        // ---- AV: 3 heads, shuffle-built a-frags
        const int srcA = 4*g + (tig >> 1);
        const bool odd = (tig & 1);
#pragma unroll
        for (int p = 0; p < 3; ++p) {
            const int h = grp + 4*p;
            const uint32_t* vb = (const uint32_t*)(KVs + tig*AV_STR + h*64 + g);
#pragma unroll
            for (int kk = 0; kk < 4; ++kk) {
                float v0 = __shfl_sync(0xffffffffu, w[p][kk][0], srcA);
                float v1 = __shfl_sync(0xffffffffu, w[p][kk][1], srcA);
                float v2 = __shfl_sync(0xffffffffu, w[p][kk][2], srcA);
                float v3 = __shfl_sync(0xffffffffu, w[p][kk][3], srcA);
                float u0 = __shfl_sync(0xffffffffu, w[p][kk][0], srcA + 2);
                float u1 = __shfl_sync(0xffffffffu, w[p][kk][1], srcA + 2);
                float u2 = __shfl_sync(0xffffffffu, w[p][kk][2], srcA + 2);
                float u3 = __shfl_sync(0xffffffffu, w[p][kk][3], srcA + 2);
                float w00 = odd ? v1 : v0;
                float w10 = odd ? v3 : v2;
                float w01 = odd ? u1 : u0;
                float w11 = odd ? u3 : u2;
                uint32_t a[4];
                a[0] = cvt_tf32(w00 * iz[0][kk][0]);
                a[1] = cvt_tf32(w10 * iz[1][kk][0]);
                a[2] = cvt_tf32(w01 * iz[0][kk][1]);
                a[3] = cvt_tf32(w11 * iz[1][kk][1]);
#pragma unroll
                for (int j = 0; j < 8; ++j) {
                    uint32_t bb[2];
                    bb[0] = vb[kk*8*AV_STR + j*8];
                    bb[1] = vb[(kk*8+4)*AV_STR + j*8];
                    mma_tf32(o[p][j], a, bb);
                }
            }
        }
    }

    // ---- writeback
#pragma unroll
    for (int p = 0; p < 3; ++p) {
        const int h = grp + 4*p;
        float* Cp = g_C + (size_t)(b*SEQ + n0 + nb + g)*DM + h*64 + 2*tig;
#pragma unroll
        for (int j = 0; j < 8; ++j) {
            *(float2*)(Cp + j*8)        = make_float2(o[p][j][0], o[p][j][1]);
            *(float2*)(Cp + 8*DM + j*8) = make_float2(o[p][j][2], o[p][j][3]);
        }
    }
}

// ===========================================================================
extern "C" void kernel_launch(void* const* d_in, const int* in_sizes, int n_in,
                              void* d_out, int out_size)
{
    const float* x  = (const float*)d_in[0];
    const float* Wq = (const float*)d_in[1];
    const float* bq = (const float*)d_in[2];
    const float* Wk = (const float*)d_in[3];
    const float* bk = (const float*)d_in[4];
    const float* Wv = (const float*)d_in[5];
    const float* bv = (const float*)d_in[6];
    const float* Wo = (const float*)d_in[7];
    const float* bo = (const float*)d_in[8];
    float* out = (float*)d_out;

    float* C;
    cudaGetSymbolAddress((void**)&C, g_C);

    cudaFuncSetAttribute(attn_mma_kernel,
                         cudaFuncAttributeMaxDynamicSharedMemorySize,
                         ATTN_SMEM_BYTES);

    dim3 g3(DM/256, MTOT/128, 3);   // (3, 64, 3)
    gemm_mma_qkv<<<g3, 256>>>(x, Wq, bq, Wk, bk, Wv, bv);

    attn_mma_kernel<<<dim3(SEQ/32, BATCH), 256, ATTN_SMEM_BYTES>>>();

    dim3 gg(DM/256, MTOT/128);      // (3, 64)
    gemm_mma_one<<<gg, 256>>>(C, Wo, bo, out);
}